// round 8
// baseline (speedup 1.0000x reference)
#include <cuda_runtime.h>
#include <cuda_bf16.h>
#include <cstdint>
#include <cstddef>

#define BATCH   4
#define SLEN    4096
#define DDIM    1024
#define MTOT    (BATCH * SLEN)          // 16384

typedef __nv_bfloat16  bf16;
typedef __nv_bfloat162 bf162;

// ---------------------------------------------------------------------------
// Scratch (allocation-free rule: __device__ globals). All operands pre-split
// into bf16 hi/lo pairs so GEMM mainloops are pure bf16.
// ---------------------------------------------------------------------------
__device__ bf16 g_xhi [(size_t)MTOT * DDIM];
__device__ bf16 g_xlo [(size_t)MTOT * DDIM];
__device__ bf16 g_Wqhi[(size_t)DDIM * DDIM];
__device__ bf16 g_Wqlo[(size_t)DDIM * DDIM];
__device__ bf16 g_Wkhi[(size_t)DDIM * DDIM];
__device__ bf16 g_Wklo[(size_t)DDIM * DDIM];
__device__ bf16 g_Wvhi[(size_t)DDIM * DDIM];
__device__ bf16 g_Wvlo[(size_t)DDIM * DDIM];
__device__ bf16 g_Qhi [(size_t)MTOT * DDIM];
__device__ bf16 g_Qlo [(size_t)MTOT * DDIM];
__device__ bf16 g_Khi [(size_t)MTOT * DDIM];
__device__ bf16 g_Klo [(size_t)MTOT * DDIM];
__device__ bf16 g_Vthi[(size_t)DDIM * MTOT];   // V transposed [D, MTOT]
__device__ bf16 g_Vtlo[(size_t)DDIM * MTOT];
__device__ float g_S  [(size_t)MTOT * SLEN];   // fp32 scores (softmax input)
__device__ bf16 g_Phi [(size_t)MTOT * SLEN];
__device__ bf16 g_Plo [(size_t)MTOT * SLEN];

// ---------------------------------------------------------------------------
// Helpers (arch-agnostic PTX only: plain sm_103 target)
// ---------------------------------------------------------------------------
__device__ __forceinline__ uint32_t smem_u32(const void* p) {
    uint32_t a;
    asm("{ .reg .u64 t; cvta.to.shared.u64 t, %1; cvt.u32.u64 %0, t; }" : "=r"(a) : "l"(p));
    return a;
}
__device__ __forceinline__ void ldsm4(uint32_t& r0, uint32_t& r1, uint32_t& r2, uint32_t& r3,
                                      uint32_t addr) {
    asm volatile("ldmatrix.sync.aligned.m8n8.x4.shared.b16 {%0,%1,%2,%3}, [%4];"
                 : "=r"(r0), "=r"(r1), "=r"(r2), "=r"(r3) : "r"(addr));
}
__device__ __forceinline__ void mma16816(float* c, const uint32_t* a, const uint32_t* b) {
    asm volatile(
        "mma.sync.aligned.m16n8k16.row.col.f32.bf16.bf16.f32 "
        "{%0,%1,%2,%3}, {%4,%5,%6,%7}, {%8,%9}, {%0,%1,%2,%3};"
        : "+f"(c[0]), "+f"(c[1]), "+f"(c[2]), "+f"(c[3])
        : "r"(a[0]), "r"(a[1]), "r"(a[2]), "r"(a[3]), "r"(b[0]), "r"(b[1]));
}
__device__ __forceinline__ void cpasync16(uint32_t dst, const void* src) {
    asm volatile("cp.async.cg.shared.global [%0], [%1], 16;" :: "r"(dst), "l"(src));
}
__device__ __forceinline__ void split2(float x, float y, bf162& h, bf162& l) {
    h = __floats2bfloat162_rn(x, y);
    float2 f = __bfloat1622float2(h);
    l = __floats2bfloat162_rn(x - f.x, y - f.y);
}

// ---------------------------------------------------------------------------
// fp32 -> bf16 hi/lo split (elementwise). n divisible by 1024.
// ---------------------------------------------------------------------------
__global__ __launch_bounds__(256) void conv_split(
    const float* __restrict__ src, bf16* __restrict__ hi, bf16* __restrict__ lo)
{
    size_t i = ((size_t)blockIdx.x * 256 + threadIdx.x) * 4;
    float4 v = *(const float4*)(src + i);
    bf162 h0, l0, h1, l1;
    split2(v.x, v.y, h0, l0);
    split2(v.z, v.w, h1, l1);
    *(bf162*)(hi + i)     = h0;
    *(bf162*)(hi + i + 2) = h1;
    *(bf162*)(lo + i)     = l0;
    *(bf162*)(lo + i + 2) = l1;
}

// ---------------------------------------------------------------------------
// Pure-bf16 NT GEMM (3-pass fp32 emulation): C = sum_k A[m,k]*B[n,k]
// CTA tile 256x128, warp tile 64x64 (4 m-warps x 2 n-warps), K-chunk 64,
// 2-stage cp.async pipeline, one __syncthreads per chunk. 256 threads.
// Pass-major MMA order: dependent MMAs on the same accumulator are 8 apart.
// mode 0: fp32 C.  mode 1: bf16 hi/lo row-major.  mode 2: bf16 hi/lo transposed.
// ---------------------------------------------------------------------------
#define KC       64
#define LDT      72                         // padded row stride (bf16) -> 144 B
#define A_MAT    (256 * LDT * 2)            // 36864 B (256 rows)
#define B_MAT    (128 * LDT * 2)            // 18432 B (128 rows)
#define OFF_AHI  0
#define OFF_ALO  (A_MAT)
#define OFF_BHI  (2 * A_MAT)
#define OFF_BLO  (2 * A_MAT + B_MAT)
#define STAGE_B  (2 * A_MAT + 2 * B_MAT)    // 110592 B
#define SMEM_DYN (2 * STAGE_B)              // 221184 B

__global__ __launch_bounds__(256, 1) void gemm_bf(
    const bf16* __restrict__ Ahi, const bf16* __restrict__ Alo,
    const bf16* __restrict__ Bhi, const bf16* __restrict__ Blo,
    float* __restrict__ Cf, bf16* __restrict__ Chi, bf16* __restrict__ Clo,
    int lda, int ldb, int ldc, int K, int mode,
    size_t sA, size_t sB, size_t sC)
{
    extern __shared__ char smem[];
    Ahi += (size_t)blockIdx.z * sA;  Alo += (size_t)blockIdx.z * sA;
    Bhi += (size_t)blockIdx.z * sB;  Blo += (size_t)blockIdx.z * sB;

    const int tid  = threadIdx.x;
    const int lane = tid & 31;
    const int wid  = tid >> 5;
    const int bm   = blockIdx.y * 256;
    const int bn   = blockIdx.x * 128;
    const int m_warp = (wid & 3) * 64;      // 4 warps along M (64 each)
    const int n_warp = (wid >> 2) * 64;     // 2 warps along N (64 each)

    const uint32_t sbase = smem_u32(smem);

    // ldmatrix per-lane byte offsets within a matrix tile
    const uint32_t aoff = (uint32_t)((m_warp + (lane & 15)) * (LDT * 2) + ((lane >> 4) * 8) * 2);
    const uint32_t boff = (uint32_t)((n_warp + (lane & 7) + ((lane & 16) ? 8 : 0)) * (LDT * 2)
                                     + ((lane & 8) ? 8 : 0) * 2);

    float acc[4][8][4];
    #pragma unroll
    for (int t = 0; t < 4; t++)
        #pragma unroll
        for (int n = 0; n < 8; n++)
            #pragma unroll
            for (int q = 0; q < 4; q++) acc[t][n][q] = 0.0f;

    const int nk = K / KC;

    // cp.async issue of one chunk into one stage buffer.
    auto issue = [&](int buf, int c) {
        const int k0 = c * KC;
        const uint32_t sb = sbase + buf * STAGE_B;
        // A: 256 rows x 8 chunks of 16B => 2048 insts, 8 per thread
        #pragma unroll
        for (int i = 0; i < 8; i++) {
            const int l   = tid + i * 256;
            const int row = l >> 3;
            const int ch  = (l & 7) * 16;
            const uint32_t soff = (uint32_t)(row * (LDT * 2)) + ch;
            const size_t ga = (size_t)(bm + row) * lda + k0;
            cpasync16(sb + OFF_AHI + soff, (const char*)(Ahi + ga) + ch);
            cpasync16(sb + OFF_ALO + soff, (const char*)(Alo + ga) + ch);
        }
        // B: 128 rows x 8 chunks => 1024 insts, 4 per thread
        #pragma unroll
        for (int i = 0; i < 4; i++) {
            const int l   = tid + i * 256;
            const int row = l >> 3;
            const int ch  = (l & 7) * 16;
            const uint32_t soff = (uint32_t)(row * (LDT * 2)) + ch;
            const size_t gb = (size_t)(bn + row) * ldb + k0;
            cpasync16(sb + OFF_BHI + soff, (const char*)(Bhi + gb) + ch);
            cpasync16(sb + OFF_BLO + soff, (const char*)(Blo + gb) + ch);
        }
    };

    // compute one chunk (4 ks-slabs of K=16), pass-major within each t
    auto compute = [&](int buf) {
        const uint32_t base = sbase + buf * STAGE_B;
        #pragma unroll
        for (int ks = 0; ks < 4; ks++) {
            const uint32_t kb = (uint32_t)ks * 32;        // 16 bf16 = 32 B
            uint32_t bh[4][4], bl[4][4];
            #pragma unroll
            for (int u = 0; u < 4; u++) {
                ldsm4(bh[u][0], bh[u][1], bh[u][2], bh[u][3],
                      base + OFF_BHI + boff + u * (16 * LDT * 2) + kb);
                ldsm4(bl[u][0], bl[u][1], bl[u][2], bl[u][3],
                      base + OFF_BLO + boff + u * (16 * LDT * 2) + kb);
            }
            #pragma unroll
            for (int t = 0; t < 4; t++) {
                uint32_t ah[4], al[4];
                ldsm4(ah[0], ah[1], ah[2], ah[3],
                      base + OFF_AHI + aoff + t * (16 * LDT * 2) + kb);
                ldsm4(al[0], al[1], al[2], al[3],
                      base + OFF_ALO + aoff + t * (16 * LDT * 2) + kb);
                // pass-major: 8 independent MMAs between reuses of acc[t][n]
                #pragma unroll
                for (int n = 0; n < 8; n++)
                    mma16816(acc[t][n], ah, &bh[n >> 1][(n & 1) * 2]);   // hi*hi
                #pragma unroll
                for (int n = 0; n < 8; n++)
                    mma16816(acc[t][n], ah, &bl[n >> 1][(n & 1) * 2]);   // hi*lo
                #pragma unroll
                for (int n = 0; n < 8; n++)
                    mma16816(acc[t][n], al, &bh[n >> 1][(n & 1) * 2]);   // lo*hi
            }
        }
    };

    // ---- pipeline: 2 stages, one barrier per chunk ----
    issue(0, 0);
    asm volatile("cp.async.commit_group;" ::: "memory");

    for (int c = 0; c < nk; ++c) {
        asm volatile("cp.async.wait_group 0;" ::: "memory");
        __syncthreads();
        if (c + 1 < nk) {
            issue((c + 1) & 1, c + 1);
            asm volatile("cp.async.commit_group;" ::: "memory");
        }
        compute(c & 1);
    }

    // ---- epilogue ----
    #pragma unroll
    for (int t = 0; t < 4; t++)
        #pragma unroll
        for (int n = 0; n < 8; n++) {
            const int row = bm + m_warp + t * 16 + (lane >> 2);
            const int col = bn + n_warp + n * 8 + (lane & 3) * 2;
            if (mode == 0) {
                float* C0 = Cf + (size_t)blockIdx.z * sC;
                *(float2*)(C0 + (size_t)row * ldc + col) =
                    make_float2(acc[t][n][0], acc[t][n][1]);
                *(float2*)(C0 + (size_t)(row + 8) * ldc + col) =
                    make_float2(acc[t][n][2], acc[t][n][3]);
            } else if (mode == 1) {
                bf162 h, l;
                split2(acc[t][n][0], acc[t][n][1], h, l);
                *(bf162*)(Chi + (size_t)row * ldc + col) = h;
                *(bf162*)(Clo + (size_t)row * ldc + col) = l;
                split2(acc[t][n][2], acc[t][n][3], h, l);
                *(bf162*)(Chi + (size_t)(row + 8) * ldc + col) = h;
                *(bf162*)(Clo + (size_t)(row + 8) * ldc + col) = l;
            } else {
                #pragma unroll
                for (int q = 0; q < 4; q++) {
                    const int r  = row + (q >> 1) * 8;
                    const int cc = col + (q & 1);
                    bf16 h = __float2bfloat16_rn(acc[t][n][q]);
                    bf16 l = __float2bfloat16_rn(acc[t][n][q] - __bfloat162float(h));
                    Chi[(size_t)cc * ldc + r] = h;
                    Clo[(size_t)cc * ldc + r] = l;
                }
            }
        }
}

// ---------------------------------------------------------------------------
// Row softmax over 4096 fp32 scores -> bf16 hi/lo probabilities.
// ---------------------------------------------------------------------------
__global__ __launch_bounds__(256) void softmax_split_kernel(
    const float* __restrict__ Sm, bf16* __restrict__ Phi, bf16* __restrict__ Plo)
{
    const float* row = Sm + (size_t)blockIdx.x * SLEN;
    bf16* ph = Phi + (size_t)blockIdx.x * SLEN;
    bf16* pl = Plo + (size_t)blockIdx.x * SLEN;
    const int t    = threadIdx.x;
    const int lane = t & 31;
    const int warp = t >> 5;

    __shared__ float red[8];

    float v[16];
    float mx = -1e30f;
    #pragma unroll
    for (int i = 0; i < 16; i++) {
        v[i] = row[t + (i << 8)];
        mx = fmaxf(mx, v[i]);
    }
    #pragma unroll
    for (int o = 16; o > 0; o >>= 1)
        mx = fmaxf(mx, __shfl_xor_sync(0xffffffffu, mx, o));
    if (lane == 0) red[warp] = mx;
    __syncthreads();
    float rmax = red[0];
    #pragma unroll
    for (int i = 1; i < 8; i++) rmax = fmaxf(rmax, red[i]);

    float sum = 0.0f;
    #pragma unroll
    for (int i = 0; i < 16; i++) {
        v[i] = __expf(v[i] - rmax);
        sum += v[i];
    }
    #pragma unroll
    for (int o = 16; o > 0; o >>= 1)
        sum += __shfl_xor_sync(0xffffffffu, sum, o);
    __syncthreads();
    if (lane == 0) red[warp] = sum;
    __syncthreads();
    float rsum = 0.0f;
    #pragma unroll
    for (int i = 0; i < 8; i++) rsum += red[i];

    const float inv = 1.0f / rsum;
    #pragma unroll
    for (int i = 0; i < 16; i++) {
        float p = v[i] * inv;
        bf16 h = __float2bfloat16_rn(p);
        ph[t + (i << 8)] = h;
        pl[t + (i << 8)] = __float2bfloat16_rn(p - __bfloat162float(h));
    }
}

// ---------------------------------------------------------------------------
// Final epilogue: y = attended + x;  out = y / ||y||_2 per 1024-row.
// ---------------------------------------------------------------------------
__global__ __launch_bounds__(256) void epilogue_kernel(
    const float* __restrict__ x, float* __restrict__ out)
{
    const size_t base = (size_t)blockIdx.x * DDIM;
    const int t    = threadIdx.x;
    const int lane = t & 31;
    const int warp = t >> 5;

    __shared__ float red[8];

    float4 a  = *(const float4*)(out + base + t * 4);
    float4 xv = *(const float4*)(x   + base + t * 4);
    float y0 = a.x + xv.x, y1 = a.y + xv.y, y2 = a.z + xv.z, y3 = a.w + xv.w;

    float ss = y0 * y0 + y1 * y1 + y2 * y2 + y3 * y3;
    #pragma unroll
    for (int o = 16; o > 0; o >>= 1)
        ss += __shfl_xor_sync(0xffffffffu, ss, o);
    if (lane == 0) red[warp] = ss;
    __syncthreads();
    float tot = 0.0f;
    #pragma unroll
    for (int i = 0; i < 8; i++) tot += red[i];

    const float inv = 1.0f / sqrtf(tot);
    *(float4*)(out + base + t * 4) =
        make_float4(y0 * inv, y1 * inv, y2 * inv, y3 * inv);
}

// ---------------------------------------------------------------------------
// Launch
// ---------------------------------------------------------------------------
extern "C" void kernel_launch(void* const* d_in, const int* in_sizes, int n_in,
                              void* d_out, int out_size)
{
    const float* x  = (const float*)d_in[0];
    const float* Wq = (const float*)d_in[1];
    const float* Wk = (const float*)d_in[2];
    const float* Wv = (const float*)d_in[3];
    float* out = (float*)d_out;

    bf16 *xhi, *xlo, *Wqhi, *Wqlo, *Wkhi, *Wklo, *Wvhi, *Wvlo;
    bf16 *Qhi, *Qlo, *Khi, *Klo, *Vthi, *Vtlo, *Phi, *Plo;
    float* Sc;
    cudaGetSymbolAddress((void**)&xhi,  g_xhi);   cudaGetSymbolAddress((void**)&xlo,  g_xlo);
    cudaGetSymbolAddress((void**)&Wqhi, g_Wqhi);  cudaGetSymbolAddress((void**)&Wqlo, g_Wqlo);
    cudaGetSymbolAddress((void**)&Wkhi, g_Wkhi);  cudaGetSymbolAddress((void**)&Wklo, g_Wklo);
    cudaGetSymbolAddress((void**)&Wvhi, g_Wvhi);  cudaGetSymbolAddress((void**)&Wvlo, g_Wvlo);
    cudaGetSymbolAddress((void**)&Qhi,  g_Qhi);   cudaGetSymbolAddress((void**)&Qlo,  g_Qlo);
    cudaGetSymbolAddress((void**)&Khi,  g_Khi);   cudaGetSymbolAddress((void**)&Klo,  g_Klo);
    cudaGetSymbolAddress((void**)&Vthi, g_Vthi);  cudaGetSymbolAddress((void**)&Vtlo, g_Vtlo);
    cudaGetSymbolAddress((void**)&Phi,  g_Phi);   cudaGetSymbolAddress((void**)&Plo,  g_Plo);
    cudaGetSymbolAddress((void**)&Sc,   g_S);

    cudaFuncSetAttribute(gemm_bf, cudaFuncAttributeMaxDynamicSharedMemorySize, SMEM_DYN);

    const size_t sQKV = (size_t)SLEN * DDIM;
    const size_t sSS  = (size_t)SLEN * SLEN;
    dim3 blk(256);

    // 0) split inputs to bf16 hi/lo
    conv_split<<<(MTOT * DDIM) / 1024, blk>>>(x,  xhi,  xlo);
    conv_split<<<(DDIM * DDIM) / 1024, blk>>>(Wq, Wqhi, Wqlo);
    conv_split<<<(DDIM * DDIM) / 1024, blk>>>(Wk, Wkhi, Wklo);
    conv_split<<<(DDIM * DDIM) / 1024, blk>>>(Wv, Wvhi, Wvlo);

    // 1) projections (NT): Q/K as hi/lo pairs; V written transposed hi/lo
    dim3 gqkv(DDIM / 128, MTOT / 256, 1);    // (8, 64)
    gemm_bf<<<gqkv, blk, SMEM_DYN>>>(xhi, xlo, Wqhi, Wqlo, nullptr, Qhi, Qlo,
                                     DDIM, DDIM, DDIM, DDIM, 1, 0, 0, 0);
    gemm_bf<<<gqkv, blk, SMEM_DYN>>>(xhi, xlo, Wkhi, Wklo, nullptr, Khi, Klo,
                                     DDIM, DDIM, DDIM, DDIM, 1, 0, 0, 0);
    gemm_bf<<<gqkv, blk, SMEM_DYN>>>(xhi, xlo, Wvhi, Wvlo, nullptr, Vthi, Vtlo,
                                     DDIM, DDIM, MTOT, DDIM, 2, 0, 0, 0);

    // 2) scores = Q @ K^T per batch (fp32 out)
    dim3 gsc(SLEN / 128, SLEN / 256, BATCH); // (32, 16, 4)
    gemm_bf<<<gsc, blk, SMEM_DYN>>>(Qhi, Qlo, Khi, Klo, Sc, nullptr, nullptr,
                                    DDIM, DDIM, SLEN, DDIM, 0, sQKV, sQKV, sSS);

    // 3) softmax -> P hi/lo (BETA = 1)
    softmax_split_kernel<<<MTOT, blk>>>(Sc, Phi, Plo);

    // 4) attended = P @ Vt^T per batch (fp32 out into d_out)
    dim3 gav(DDIM / 128, SLEN / 256, BATCH); // (8, 16, 4)
    gemm_bf<<<gav, blk, SMEM_DYN>>>(Phi, Plo, Vthi, Vtlo, out, nullptr, nullptr,
                                    SLEN, MTOT, DDIM, SLEN, 0,
                                    sSS, (size_t)SLEN, sQKV);

    // 5) y = attended + x; L2 normalize
    epilogue_kernel<<<MTOT, blk>>>(x, out);
}

// round 9
// speedup vs baseline: 1.0410x; 1.0410x over previous
#include <cuda_runtime.h>
#include <cuda_bf16.h>
#include <cstdint>
#include <cstddef>

#define BATCH   4
#define SLEN    4096
#define DDIM    1024
#define MTOT    (BATCH * SLEN)          // 16384

typedef __nv_bfloat16  bf16;
typedef __nv_bfloat162 bf162;

// ---------------------------------------------------------------------------
// Scratch (allocation-free rule: __device__ globals). All operands pre-split
// into bf16 hi/lo pairs so GEMM mainloops are pure bf16.
// ---------------------------------------------------------------------------
__device__ bf16 g_xhi [(size_t)MTOT * DDIM];
__device__ bf16 g_xlo [(size_t)MTOT * DDIM];
__device__ bf16 g_Wqhi[(size_t)DDIM * DDIM];
__device__ bf16 g_Wqlo[(size_t)DDIM * DDIM];
__device__ bf16 g_Wkhi[(size_t)DDIM * DDIM];
__device__ bf16 g_Wklo[(size_t)DDIM * DDIM];
__device__ bf16 g_Wvhi[(size_t)DDIM * DDIM];
__device__ bf16 g_Wvlo[(size_t)DDIM * DDIM];
__device__ bf16 g_Qhi [(size_t)MTOT * DDIM];
__device__ bf16 g_Qlo [(size_t)MTOT * DDIM];
__device__ bf16 g_Khi [(size_t)MTOT * DDIM];
__device__ bf16 g_Klo [(size_t)MTOT * DDIM];
__device__ bf16 g_Vthi[(size_t)DDIM * MTOT];   // V transposed [D, MTOT]
__device__ bf16 g_Vtlo[(size_t)DDIM * MTOT];
__device__ float g_S  [(size_t)MTOT * SLEN];   // fp32 scores (softmax input)
__device__ bf16 g_Phi [(size_t)MTOT * SLEN];
__device__ bf16 g_Plo [(size_t)MTOT * SLEN];

// ---------------------------------------------------------------------------
// Helpers (arch-agnostic PTX only: plain sm_103 target)
// ---------------------------------------------------------------------------
__device__ __forceinline__ uint32_t smem_u32(const void* p) {
    uint32_t a;
    asm("{ .reg .u64 t; cvta.to.shared.u64 t, %1; cvt.u32.u64 %0, t; }" : "=r"(a) : "l"(p));
    return a;
}
__device__ __forceinline__ void ldsm4(uint32_t& r0, uint32_t& r1, uint32_t& r2, uint32_t& r3,
                                      uint32_t addr) {
    asm volatile("ldmatrix.sync.aligned.m8n8.x4.shared.b16 {%0,%1,%2,%3}, [%4];"
                 : "=r"(r0), "=r"(r1), "=r"(r2), "=r"(r3) : "r"(addr));
}
__device__ __forceinline__ void mma16816(float* c, const uint32_t* a, const uint32_t* b) {
    asm volatile(
        "mma.sync.aligned.m16n8k16.row.col.f32.bf16.bf16.f32 "
        "{%0,%1,%2,%3}, {%4,%5,%6,%7}, {%8,%9}, {%0,%1,%2,%3};"
        : "+f"(c[0]), "+f"(c[1]), "+f"(c[2]), "+f"(c[3])
        : "r"(a[0]), "r"(a[1]), "r"(a[2]), "r"(a[3]), "r"(b[0]), "r"(b[1]));
}
__device__ __forceinline__ void cpasync16(uint32_t dst, const void* src) {
    asm volatile("cp.async.cg.shared.global [%0], [%1], 16;" :: "r"(dst), "l"(src));
}
__device__ __forceinline__ void split2(float x, float y, bf162& h, bf162& l) {
    h = __floats2bfloat162_rn(x, y);
    float2 f = __bfloat1622float2(h);
    l = __floats2bfloat162_rn(x - f.x, y - f.y);
}

// ---------------------------------------------------------------------------
// fp32 -> bf16 hi/lo split (elementwise). n divisible by 1024.
// ---------------------------------------------------------------------------
__global__ __launch_bounds__(256) void conv_split(
    const float* __restrict__ src, bf16* __restrict__ hi, bf16* __restrict__ lo)
{
    size_t i = ((size_t)blockIdx.x * 256 + threadIdx.x) * 4;
    float4 v = *(const float4*)(src + i);
    bf162 h0, l0, h1, l1;
    split2(v.x, v.y, h0, l0);
    split2(v.z, v.w, h1, l1);
    *(bf162*)(hi + i)     = h0;
    *(bf162*)(hi + i + 2) = h1;
    *(bf162*)(lo + i)     = l0;
    *(bf162*)(lo + i + 2) = l1;
}

// ---------------------------------------------------------------------------
// Pure-bf16 NT GEMM (3-pass fp32 emulation): C = sum_k A[m,k]*B[n,k]
// CTA tile 128x128, warp tile 32x64, K-chunk 32, 2-stage cp.async pipeline,
// one __syncthreads per chunk. 256 threads, TWO CTAs per SM (4 warps/SMSP).
// mode 0: fp32 C.  mode 1: bf16 hi/lo row-major.  mode 2: bf16 hi/lo transposed.
// ---------------------------------------------------------------------------
#define KC       32
#define LDT      40                         // padded row stride (bf16) -> 80 B
#define MAT_B    (128 * LDT * 2)            // 10240 B
#define STAGE_B  (4 * MAT_B)                // Ahi, Alo, Bhi, Blo = 40960 B
#define SMEM_DYN (2 * STAGE_B)              // 81920 B per CTA; x2 CTA = 160 KB/SM

__global__ __launch_bounds__(256, 2) void gemm_bf(
    const bf16* __restrict__ Ahi, const bf16* __restrict__ Alo,
    const bf16* __restrict__ Bhi, const bf16* __restrict__ Blo,
    float* __restrict__ Cf, bf16* __restrict__ Chi, bf16* __restrict__ Clo,
    int lda, int ldb, int ldc, int K, int mode,
    size_t sA, size_t sB, size_t sC)
{
    extern __shared__ char smem[];
    Ahi += (size_t)blockIdx.z * sA;  Alo += (size_t)blockIdx.z * sA;
    Bhi += (size_t)blockIdx.z * sB;  Blo += (size_t)blockIdx.z * sB;

    const int tid  = threadIdx.x;
    const int lane = tid & 31;
    const int wid  = tid >> 5;
    const int bm   = blockIdx.y * 128;
    const int bn   = blockIdx.x * 128;
    const int m_warp = (wid & 3) * 32;      // 4 warps along M (32 each)
    const int n_warp = (wid >> 2) * 64;     // 2 warps along N (64 each)

    const uint32_t sbase = smem_u32(smem);

    // ldmatrix per-lane byte offsets within a matrix tile
    const uint32_t aoff = (uint32_t)((m_warp + (lane & 15)) * (LDT * 2) + ((lane >> 4) * 8) * 2);
    const uint32_t boff = (uint32_t)((n_warp + (lane & 7) + ((lane & 16) ? 8 : 0)) * (LDT * 2)
                                     + ((lane & 8) ? 8 : 0) * 2);

    float acc[2][8][4];
    #pragma unroll
    for (int t = 0; t < 2; t++)
        #pragma unroll
        for (int n = 0; n < 8; n++)
            #pragma unroll
            for (int q = 0; q < 4; q++) acc[t][n][q] = 0.0f;

    const int nk = K / KC;

    // cp.async issue of one chunk into one stage buffer.
    // Per matrix: 128 rows x 4 chunks of 16B = 512; 4 matrices = 2048; 8/thread.
    auto issue = [&](int buf, int c) {
        const int k0 = c * KC;
        const uint32_t sb = sbase + buf * STAGE_B;
        #pragma unroll
        for (int i = 0; i < 2; i++) {
            const int l   = tid + i * 256;
            const int row = l >> 2;
            const int ch  = (l & 3) * 16;
            const uint32_t soff = (uint32_t)(row * (LDT * 2)) + ch;
            const size_t ga = (size_t)(bm + row) * lda + k0;
            const size_t gb = (size_t)(bn + row) * ldb + k0;
            cpasync16(sb + 0 * MAT_B + soff, (const char*)(Ahi + ga) + ch);
            cpasync16(sb + 1 * MAT_B + soff, (const char*)(Alo + ga) + ch);
            cpasync16(sb + 2 * MAT_B + soff, (const char*)(Bhi + gb) + ch);
            cpasync16(sb + 3 * MAT_B + soff, (const char*)(Blo + gb) + ch);
        }
    };

    // compute one chunk (2 ks-slabs of K=16), pass-major within each t
    auto compute = [&](int buf) {
        const uint32_t base = sbase + buf * STAGE_B;
        #pragma unroll
        for (int ks = 0; ks < 2; ks++) {
            const uint32_t kb = (uint32_t)ks * 32;        // 16 bf16 = 32 B
            uint32_t bh[4][4], bl[4][4];
            #pragma unroll
            for (int u = 0; u < 4; u++) {
                ldsm4(bh[u][0], bh[u][1], bh[u][2], bh[u][3],
                      base + 2 * MAT_B + boff + u * (16 * LDT * 2) + kb);
                ldsm4(bl[u][0], bl[u][1], bl[u][2], bl[u][3],
                      base + 3 * MAT_B + boff + u * (16 * LDT * 2) + kb);
            }
            #pragma unroll
            for (int t = 0; t < 2; t++) {
                uint32_t ah[4], al[4];
                ldsm4(ah[0], ah[1], ah[2], ah[3],
                      base + 0 * MAT_B + aoff + t * (16 * LDT * 2) + kb);
                ldsm4(al[0], al[1], al[2], al[3],
                      base + 1 * MAT_B + aoff + t * (16 * LDT * 2) + kb);
                #pragma unroll
                for (int n = 0; n < 8; n++)
                    mma16816(acc[t][n], ah, &bh[n >> 1][(n & 1) * 2]);   // hi*hi
                #pragma unroll
                for (int n = 0; n < 8; n++)
                    mma16816(acc[t][n], ah, &bl[n >> 1][(n & 1) * 2]);   // hi*lo
                #pragma unroll
                for (int n = 0; n < 8; n++)
                    mma16816(acc[t][n], al, &bh[n >> 1][(n & 1) * 2]);   // lo*hi
            }
        }
    };

    // ---- pipeline: 2 stages, one barrier per chunk ----
    issue(0, 0);
    asm volatile("cp.async.commit_group;" ::: "memory");

    for (int c = 0; c < nk; ++c) {
        asm volatile("cp.async.wait_group 0;" ::: "memory");
        __syncthreads();
        if (c + 1 < nk) {
            issue((c + 1) & 1, c + 1);
            asm volatile("cp.async.commit_group;" ::: "memory");
        }
        compute(c & 1);
    }

    // ---- epilogue ----
    #pragma unroll
    for (int t = 0; t < 2; t++)
        #pragma unroll
        for (int n = 0; n < 8; n++) {
            const int row = bm + m_warp + t * 16 + (lane >> 2);
            const int col = bn + n_warp + n * 8 + (lane & 3) * 2;
            if (mode == 0) {
                float* C0 = Cf + (size_t)blockIdx.z * sC;
                *(float2*)(C0 + (size_t)row * ldc + col) =
                    make_float2(acc[t][n][0], acc[t][n][1]);
                *(float2*)(C0 + (size_t)(row + 8) * ldc + col) =
                    make_float2(acc[t][n][2], acc[t][n][3]);
            } else if (mode == 1) {
                bf162 h, l;
                split2(acc[t][n][0], acc[t][n][1], h, l);
                *(bf162*)(Chi + (size_t)row * ldc + col) = h;
                *(bf162*)(Clo + (size_t)row * ldc + col) = l;
                split2(acc[t][n][2], acc[t][n][3], h, l);
                *(bf162*)(Chi + (size_t)(row + 8) * ldc + col) = h;
                *(bf162*)(Clo + (size_t)(row + 8) * ldc + col) = l;
            } else {
                #pragma unroll
                for (int q = 0; q < 4; q++) {
                    const int r  = row + (q >> 1) * 8;
                    const int cc = col + (q & 1);
                    bf16 h = __float2bfloat16_rn(acc[t][n][q]);
                    bf16 l = __float2bfloat16_rn(acc[t][n][q] - __bfloat162float(h));
                    Chi[(size_t)cc * ldc + r] = h;
                    Clo[(size_t)cc * ldc + r] = l;
                }
            }
        }
}

// ---------------------------------------------------------------------------
// Row softmax over 4096 fp32 scores -> bf16 hi/lo probabilities.
// ---------------------------------------------------------------------------
__global__ __launch_bounds__(256) void softmax_split_kernel(
    const float* __restrict__ Sm, bf16* __restrict__ Phi, bf16* __restrict__ Plo)
{
    const float* row = Sm + (size_t)blockIdx.x * SLEN;
    bf16* ph = Phi + (size_t)blockIdx.x * SLEN;
    bf16* pl = Plo + (size_t)blockIdx.x * SLEN;
    const int t    = threadIdx.x;
    const int lane = t & 31;
    const int warp = t >> 5;

    __shared__ float red[8];

    float v[16];
    float mx = -1e30f;
    #pragma unroll
    for (int i = 0; i < 16; i++) {
        v[i] = row[t + (i << 8)];
        mx = fmaxf(mx, v[i]);
    }
    #pragma unroll
    for (int o = 16; o > 0; o >>= 1)
        mx = fmaxf(mx, __shfl_xor_sync(0xffffffffu, mx, o));
    if (lane == 0) red[warp] = mx;
    __syncthreads();
    float rmax = red[0];
    #pragma unroll
    for (int i = 1; i < 8; i++) rmax = fmaxf(rmax, red[i]);

    float sum = 0.0f;
    #pragma unroll
    for (int i = 0; i < 16; i++) {
        v[i] = __expf(v[i] - rmax);
        sum += v[i];
    }
    #pragma unroll
    for (int o = 16; o > 0; o >>= 1)
        sum += __shfl_xor_sync(0xffffffffu, sum, o);
    __syncthreads();
    if (lane == 0) red[warp] = sum;
    __syncthreads();
    float rsum = 0.0f;
    #pragma unroll
    for (int i = 0; i < 8; i++) rsum += red[i];

    const float inv = 1.0f / rsum;
    #pragma unroll
    for (int i = 0; i < 16; i++) {
        float p = v[i] * inv;
        bf16 h = __float2bfloat16_rn(p);
        ph[t + (i << 8)] = h;
        pl[t + (i << 8)] = __float2bfloat16_rn(p - __bfloat162float(h));
    }
}

// ---------------------------------------------------------------------------
// Final epilogue: y = attended + x;  out = y / ||y||_2 per 1024-row.
// ---------------------------------------------------------------------------
__global__ __launch_bounds__(256) void epilogue_kernel(
    const float* __restrict__ x, float* __restrict__ out)
{
    const size_t base = (size_t)blockIdx.x * DDIM;
    const int t    = threadIdx.x;
    const int lane = t & 31;
    const int warp = t >> 5;

    __shared__ float red[8];

    float4 a  = *(const float4*)(out + base + t * 4);
    float4 xv = *(const float4*)(x   + base + t * 4);
    float y0 = a.x + xv.x, y1 = a.y + xv.y, y2 = a.z + xv.z, y3 = a.w + xv.w;

    float ss = y0 * y0 + y1 * y1 + y2 * y2 + y3 * y3;
    #pragma unroll
    for (int o = 16; o > 0; o >>= 1)
        ss += __shfl_xor_sync(0xffffffffu, ss, o);
    if (lane == 0) red[warp] = ss;
    __syncthreads();
    float tot = 0.0f;
    #pragma unroll
    for (int i = 0; i < 8; i++) tot += red[i];

    const float inv = 1.0f / sqrtf(tot);
    *(float4*)(out + base + t * 4) =
        make_float4(y0 * inv, y1 * inv, y2 * inv, y3 * inv);
}

// ---------------------------------------------------------------------------
// Launch
// ---------------------------------------------------------------------------
extern "C" void kernel_launch(void* const* d_in, const int* in_sizes, int n_in,
                              void* d_out, int out_size)
{
    const float* x  = (const float*)d_in[0];
    const float* Wq = (const float*)d_in[1];
    const float* Wk = (const float*)d_in[2];
    const float* Wv = (const float*)d_in[3];
    float* out = (float*)d_out;

    bf16 *xhi, *xlo, *Wqhi, *Wqlo, *Wkhi, *Wklo, *Wvhi, *Wvlo;
    bf16 *Qhi, *Qlo, *Khi, *Klo, *Vthi, *Vtlo, *Phi, *Plo;
    float* Sc;
    cudaGetSymbolAddress((void**)&xhi,  g_xhi);   cudaGetSymbolAddress((void**)&xlo,  g_xlo);
    cudaGetSymbolAddress((void**)&Wqhi, g_Wqhi);  cudaGetSymbolAddress((void**)&Wqlo, g_Wqlo);
    cudaGetSymbolAddress((void**)&Wkhi, g_Wkhi);  cudaGetSymbolAddress((void**)&Wklo, g_Wklo);
    cudaGetSymbolAddress((void**)&Wvhi, g_Wvhi);  cudaGetSymbolAddress((void**)&Wvlo, g_Wvlo);
    cudaGetSymbolAddress((void**)&Qhi,  g_Qhi);   cudaGetSymbolAddress((void**)&Qlo,  g_Qlo);
    cudaGetSymbolAddress((void**)&Khi,  g_Khi);   cudaGetSymbolAddress((void**)&Klo,  g_Klo);
    cudaGetSymbolAddress((void**)&Vthi, g_Vthi);  cudaGetSymbolAddress((void**)&Vtlo, g_Vtlo);
    cudaGetSymbolAddress((void**)&Phi,  g_Phi);   cudaGetSymbolAddress((void**)&Plo,  g_Plo);
    cudaGetSymbolAddress((void**)&Sc,   g_S);

    cudaFuncSetAttribute(gemm_bf, cudaFuncAttributeMaxDynamicSharedMemorySize, SMEM_DYN);

    const size_t sQKV = (size_t)SLEN * DDIM;
    const size_t sSS  = (size_t)SLEN * SLEN;
    dim3 blk(256);

    // 0) split inputs to bf16 hi/lo
    conv_split<<<(MTOT * DDIM) / 1024, blk>>>(x,  xhi,  xlo);
    conv_split<<<(DDIM * DDIM) / 1024, blk>>>(Wq, Wqhi, Wqlo);
    conv_split<<<(DDIM * DDIM) / 1024, blk>>>(Wk, Wkhi, Wklo);
    conv_split<<<(DDIM * DDIM) / 1024, blk>>>(Wv, Wvhi, Wvlo);

    // 1) projections (NT): Q/K as hi/lo pairs; V written transposed hi/lo
    dim3 gqkv(DDIM / 128, MTOT / 128, 1);    // (8, 128)
    gemm_bf<<<gqkv, blk, SMEM_DYN>>>(xhi, xlo, Wqhi, Wqlo, nullptr, Qhi, Qlo,
                                     DDIM, DDIM, DDIM, DDIM, 1, 0, 0, 0);
    gemm_bf<<<gqkv, blk, SMEM_DYN>>>(xhi, xlo, Wkhi, Wklo, nullptr, Khi, Klo,
                                     DDIM, DDIM, DDIM, DDIM, 1, 0, 0, 0);
    gemm_bf<<<gqkv, blk, SMEM_DYN>>>(xhi, xlo, Wvhi, Wvlo, nullptr, Vthi, Vtlo,
                                     DDIM, DDIM, MTOT, DDIM, 2, 0, 0, 0);

    // 2) scores = Q @ K^T per batch (fp32 out)
    dim3 gsc(SLEN / 128, SLEN / 128, BATCH); // (32, 32, 4)
    gemm_bf<<<gsc, blk, SMEM_DYN>>>(Qhi, Qlo, Khi, Klo, Sc, nullptr, nullptr,
                                    DDIM, DDIM, SLEN, DDIM, 0, sQKV, sQKV, sSS);

    // 3) softmax -> P hi/lo (BETA = 1)
    softmax_split_kernel<<<MTOT, blk>>>(Sc, Phi, Plo);

    // 4) attended = P @ Vt^T per batch (fp32 out into d_out)
    dim3 gav(DDIM / 128, SLEN / 128, BATCH); // (8, 32, 4)
    gemm_bf<<<gav, blk, SMEM_DYN>>>(Phi, Plo, Vthi, Vtlo, out, nullptr, nullptr,
                                    SLEN, MTOT, DDIM, SLEN, 0,
                                    sSS, (size_t)SLEN, sQKV);

    // 5) y = attended + x; L2 normalize
    epilogue_kernel<<<MTOT, blk>>>(x, out);
}

// round 10
// speedup vs baseline: 1.1294x; 1.0849x over previous
#include <cuda_runtime.h>
#include <cuda_bf16.h>
#include <cstdint>
#include <cstddef>

#define BATCH   4
#define SLEN    4096
#define DDIM    1024
#define MTOT    (BATCH * SLEN)          // 16384

typedef __nv_bfloat16  bf16;
typedef __nv_bfloat162 bf162;

// ---------------------------------------------------------------------------
// Scratch (allocation-free rule: __device__ globals). All operands pre-split
// into bf16 hi/lo pairs so GEMM mainloops are pure bf16.
//   scores = z·xᵀ with z = x·M, M = Wqᵀ·Wk  (K projection eliminated)
//   Vᵀ = Wv·xᵀ computed directly (coalesced), PV = P·(Vᵀ)ᵀ
// ---------------------------------------------------------------------------
__device__ bf16 g_xhi [(size_t)MTOT * DDIM];
__device__ bf16 g_xlo [(size_t)MTOT * DDIM];
__device__ bf16 g_Wqthi[(size_t)DDIM * DDIM];   // Wqᵀ rows
__device__ bf16 g_Wqtlo[(size_t)DDIM * DDIM];
__device__ bf16 g_Wkthi[(size_t)DDIM * DDIM];   // Wkᵀ rows
__device__ bf16 g_Wktlo[(size_t)DDIM * DDIM];
__device__ bf16 g_Wvhi[(size_t)DDIM * DDIM];
__device__ bf16 g_Wvlo[(size_t)DDIM * DDIM];
__device__ bf16 g_Mthi[(size_t)DDIM * DDIM];    // Mᵀ rows (M = Wqᵀ·Wk)
__device__ bf16 g_Mtlo[(size_t)DDIM * DDIM];
__device__ bf16 g_zhi [(size_t)MTOT * DDIM];    // z = x·M
__device__ bf16 g_zlo [(size_t)MTOT * DDIM];
__device__ bf16 g_Vthi[(size_t)DDIM * MTOT];    // V transposed [D, MTOT]
__device__ bf16 g_Vtlo[(size_t)DDIM * MTOT];
__device__ float g_S  [(size_t)MTOT * SLEN];    // fp32 scores (softmax input)
__device__ bf16 g_Phi [(size_t)MTOT * SLEN];
__device__ bf16 g_Plo [(size_t)MTOT * SLEN];

// ---------------------------------------------------------------------------
// Helpers (arch-agnostic PTX only: plain sm_103 target)
// ---------------------------------------------------------------------------
__device__ __forceinline__ uint32_t smem_u32(const void* p) {
    uint32_t a;
    asm("{ .reg .u64 t; cvta.to.shared.u64 t, %1; cvt.u32.u64 %0, t; }" : "=r"(a) : "l"(p));
    return a;
}
__device__ __forceinline__ void ldsm4(uint32_t& r0, uint32_t& r1, uint32_t& r2, uint32_t& r3,
                                      uint32_t addr) {
    asm volatile("ldmatrix.sync.aligned.m8n8.x4.shared.b16 {%0,%1,%2,%3}, [%4];"
                 : "=r"(r0), "=r"(r1), "=r"(r2), "=r"(r3) : "r"(addr));
}
__device__ __forceinline__ void mma16816(float* c, const uint32_t* a, const uint32_t* b) {
    asm volatile(
        "mma.sync.aligned.m16n8k16.row.col.f32.bf16.bf16.f32 "
        "{%0,%1,%2,%3}, {%4,%5,%6,%7}, {%8,%9}, {%0,%1,%2,%3};"
        : "+f"(c[0]), "+f"(c[1]), "+f"(c[2]), "+f"(c[3])
        : "r"(a[0]), "r"(a[1]), "r"(a[2]), "r"(a[3]), "r"(b[0]), "r"(b[1]));
}
__device__ __forceinline__ void cpasync16(uint32_t dst, const void* src) {
    asm volatile("cp.async.cg.shared.global [%0], [%1], 16;" :: "r"(dst), "l"(src));
}
__device__ __forceinline__ void split2(float x, float y, bf162& h, bf162& l) {
    h = __floats2bfloat162_rn(x, y);
    float2 f = __bfloat1622float2(h);
    l = __floats2bfloat162_rn(x - f.x, y - f.y);
}

// ---------------------------------------------------------------------------
// fp32 -> bf16 hi/lo split (elementwise). n divisible by 1024.
// ---------------------------------------------------------------------------
__global__ __launch_bounds__(256) void conv_split(
    const float* __restrict__ src, bf16* __restrict__ hi, bf16* __restrict__ lo)
{
    size_t i = ((size_t)blockIdx.x * 256 + threadIdx.x) * 4;
    float4 v = *(const float4*)(src + i);
    bf162 h0, l0, h1, l1;
    split2(v.x, v.y, h0, l0);
    split2(v.z, v.w, h1, l1);
    *(bf162*)(hi + i)     = h0;
    *(bf162*)(hi + i + 2) = h1;
    *(bf162*)(lo + i)     = l0;
    *(bf162*)(lo + i + 2) = l1;
}

// ---------------------------------------------------------------------------
// Transpose + split: out[i,e] = src[e,i] for 1024x1024 fp32, bf16 hi/lo out.
// 32x32 tiles, 32x8 threads.
// ---------------------------------------------------------------------------
__global__ __launch_bounds__(256) void trans_split(
    const float* __restrict__ src, bf16* __restrict__ hi, bf16* __restrict__ lo)
{
    __shared__ float t[32][33];
    const int tx = threadIdx.x & 31;
    const int ty = threadIdx.x >> 5;          // 0..7
    const int bx = blockIdx.x * 32;           // source col block
    const int by = blockIdx.y * 32;           // source row block
    #pragma unroll
    for (int i = 0; i < 4; i++)
        t[ty + i * 8][tx] = src[(size_t)(by + ty + i * 8) * DDIM + bx + tx];
    __syncthreads();
    #pragma unroll
    for (int i = 0; i < 4; i++) {
        const int r = ty + i * 8;             // output row within tile (= src col)
        float v = t[tx][r];
        bf16 h = __float2bfloat16_rn(v);
        bf16 l = __float2bfloat16_rn(v - __bfloat162float(h));
        hi[(size_t)(bx + r) * DDIM + by + tx] = h;
        lo[(size_t)(bx + r) * DDIM + by + tx] = l;
    }
}

// ---------------------------------------------------------------------------
// Pure-bf16 NT GEMM (3-pass fp32 emulation): C = sum_k A[m,k]*B[n,k]
// CTA tile 128x128, warp tile 32x64, K-chunk 32, 2-stage cp.async pipeline,
// one __syncthreads per chunk. 256 threads, TWO CTAs per SM.
// mode 0: fp32 C.  mode 1: bf16 hi/lo row-major.
// ---------------------------------------------------------------------------
#define KC       32
#define LDT      40                         // padded row stride (bf16) -> 80 B
#define MAT_B    (128 * LDT * 2)            // 10240 B
#define STAGE_B  (4 * MAT_B)                // Ahi, Alo, Bhi, Blo = 40960 B
#define SMEM_DYN (2 * STAGE_B)              // 81920 B per CTA; x2 CTA = 160 KB/SM

__global__ __launch_bounds__(256, 2) void gemm_bf(
    const bf16* __restrict__ Ahi, const bf16* __restrict__ Alo,
    const bf16* __restrict__ Bhi, const bf16* __restrict__ Blo,
    float* __restrict__ Cf, bf16* __restrict__ Chi, bf16* __restrict__ Clo,
    int lda, int ldb, int ldc, int K, int mode,
    size_t sA, size_t sB, size_t sC)
{
    extern __shared__ char smem[];
    Ahi += (size_t)blockIdx.z * sA;  Alo += (size_t)blockIdx.z * sA;
    Bhi += (size_t)blockIdx.z * sB;  Blo += (size_t)blockIdx.z * sB;

    const int tid  = threadIdx.x;
    const int lane = tid & 31;
    const int wid  = tid >> 5;
    const int bm   = blockIdx.y * 128;
    const int bn   = blockIdx.x * 128;
    const int m_warp = (wid & 3) * 32;      // 4 warps along M (32 each)
    const int n_warp = (wid >> 2) * 64;     // 2 warps along N (64 each)

    const uint32_t sbase = smem_u32(smem);

    // ldmatrix per-lane byte offsets within a matrix tile
    const uint32_t aoff = (uint32_t)((m_warp + (lane & 15)) * (LDT * 2) + ((lane >> 4) * 8) * 2);
    const uint32_t boff = (uint32_t)((n_warp + (lane & 7) + ((lane & 16) ? 8 : 0)) * (LDT * 2)
                                     + ((lane & 8) ? 8 : 0) * 2);

    float acc[2][8][4];
    #pragma unroll
    for (int t = 0; t < 2; t++)
        #pragma unroll
        for (int n = 0; n < 8; n++)
            #pragma unroll
            for (int q = 0; q < 4; q++) acc[t][n][q] = 0.0f;

    const int nk = K / KC;

    // cp.async issue of one chunk into one stage buffer.
    auto issue = [&](int buf, int c) {
        const int k0 = c * KC;
        const uint32_t sb = sbase + buf * STAGE_B;
        #pragma unroll
        for (int i = 0; i < 2; i++) {
            const int l   = tid + i * 256;
            const int row = l >> 2;
            const int ch  = (l & 3) * 16;
            const uint32_t soff = (uint32_t)(row * (LDT * 2)) + ch;
            const size_t ga = (size_t)(bm + row) * lda + k0;
            const size_t gb = (size_t)(bn + row) * ldb + k0;
            cpasync16(sb + 0 * MAT_B + soff, (const char*)(Ahi + ga) + ch);
            cpasync16(sb + 1 * MAT_B + soff, (const char*)(Alo + ga) + ch);
            cpasync16(sb + 2 * MAT_B + soff, (const char*)(Bhi + gb) + ch);
            cpasync16(sb + 3 * MAT_B + soff, (const char*)(Blo + gb) + ch);
        }
    };

    // compute one chunk (2 ks-slabs of K=16), pass-major within each t
    auto compute = [&](int buf) {
        const uint32_t base = sbase + buf * STAGE_B;
        #pragma unroll
        for (int ks = 0; ks < 2; ks++) {
            const uint32_t kb = (uint32_t)ks * 32;        // 16 bf16 = 32 B
            uint32_t bh[4][4], bl[4][4];
            #pragma unroll
            for (int u = 0; u < 4; u++) {
                ldsm4(bh[u][0], bh[u][1], bh[u][2], bh[u][3],
                      base + 2 * MAT_B + boff + u * (16 * LDT * 2) + kb);
                ldsm4(bl[u][0], bl[u][1], bl[u][2], bl[u][3],
                      base + 3 * MAT_B + boff + u * (16 * LDT * 2) + kb);
            }
            #pragma unroll
            for (int t = 0; t < 2; t++) {
                uint32_t ah[4], al[4];
                ldsm4(ah[0], ah[1], ah[2], ah[3],
                      base + 0 * MAT_B + aoff + t * (16 * LDT * 2) + kb);
                ldsm4(al[0], al[1], al[2], al[3],
                      base + 1 * MAT_B + aoff + t * (16 * LDT * 2) + kb);
                #pragma unroll
                for (int n = 0; n < 8; n++)
                    mma16816(acc[t][n], ah, &bh[n >> 1][(n & 1) * 2]);   // hi*hi
                #pragma unroll
                for (int n = 0; n < 8; n++)
                    mma16816(acc[t][n], ah, &bl[n >> 1][(n & 1) * 2]);   // hi*lo
                #pragma unroll
                for (int n = 0; n < 8; n++)
                    mma16816(acc[t][n], al, &bh[n >> 1][(n & 1) * 2]);   // lo*hi
            }
        }
    };

    // ---- pipeline: 2 stages, one barrier per chunk ----
    issue(0, 0);
    asm volatile("cp.async.commit_group;" ::: "memory");

    for (int c = 0; c < nk; ++c) {
        asm volatile("cp.async.wait_group 0;" ::: "memory");
        __syncthreads();
        if (c + 1 < nk) {
            issue((c + 1) & 1, c + 1);
            asm volatile("cp.async.commit_group;" ::: "memory");
        }
        compute(c & 1);
    }

    // ---- epilogue ----
    #pragma unroll
    for (int t = 0; t < 2; t++)
        #pragma unroll
        for (int n = 0; n < 8; n++) {
            const int row = bm + m_warp + t * 16 + (lane >> 2);
            const int col = bn + n_warp + n * 8 + (lane & 3) * 2;
            if (mode == 0) {
                float* C0 = Cf + (size_t)blockIdx.z * sC;
                *(float2*)(C0 + (size_t)row * ldc + col) =
                    make_float2(acc[t][n][0], acc[t][n][1]);
                *(float2*)(C0 + (size_t)(row + 8) * ldc + col) =
                    make_float2(acc[t][n][2], acc[t][n][3]);
            } else {
                bf162 h, l;
                split2(acc[t][n][0], acc[t][n][1], h, l);
                *(bf162*)(Chi + (size_t)row * ldc + col) = h;
                *(bf162*)(Clo + (size_t)row * ldc + col) = l;
                split2(acc[t][n][2], acc[t][n][3], h, l);
                *(bf162*)(Chi + (size_t)(row + 8) * ldc + col) = h;
                *(bf162*)(Clo + (size_t)(row + 8) * ldc + col) = l;
            }
        }
}

// ---------------------------------------------------------------------------
// Row softmax over 4096 fp32 scores -> bf16 hi/lo probabilities.
// ---------------------------------------------------------------------------
__global__ __launch_bounds__(256) void softmax_split_kernel(
    const float* __restrict__ Sm, bf16* __restrict__ Phi, bf16* __restrict__ Plo)
{
    const float* row = Sm + (size_t)blockIdx.x * SLEN;
    bf16* ph = Phi + (size_t)blockIdx.x * SLEN;
    bf16* pl = Plo + (size_t)blockIdx.x * SLEN;
    const int t    = threadIdx.x;
    const int lane = t & 31;
    const int warp = t >> 5;

    __shared__ float red[8];

    float v[16];
    float mx = -1e30f;
    #pragma unroll
    for (int i = 0; i < 16; i++) {
        v[i] = row[t + (i << 8)];
        mx = fmaxf(mx, v[i]);
    }
    #pragma unroll
    for (int o = 16; o > 0; o >>= 1)
        mx = fmaxf(mx, __shfl_xor_sync(0xffffffffu, mx, o));
    if (lane == 0) red[warp] = mx;
    __syncthreads();
    float rmax = red[0];
    #pragma unroll
    for (int i = 1; i < 8; i++) rmax = fmaxf(rmax, red[i]);

    float sum = 0.0f;
    #pragma unroll
    for (int i = 0; i < 16; i++) {
        v[i] = __expf(v[i] - rmax);
        sum += v[i];
    }
    #pragma unroll
    for (int o = 16; o > 0; o >>= 1)
        sum += __shfl_xor_sync(0xffffffffu, sum, o);
    __syncthreads();
    if (lane == 0) red[warp] = sum;
    __syncthreads();
    float rsum = 0.0f;
    #pragma unroll
    for (int i = 0; i < 8; i++) rsum += red[i];

    const float inv = 1.0f / rsum;
    #pragma unroll
    for (int i = 0; i < 16; i++) {
        float p = v[i] * inv;
        bf16 h = __float2bfloat16_rn(p);
        ph[t + (i << 8)] = h;
        pl[t + (i << 8)] = __float2bfloat16_rn(p - __bfloat162float(h));
    }
}

// ---------------------------------------------------------------------------
// Final epilogue: y = attended + x;  out = y / ||y||_2 per 1024-row.
// ---------------------------------------------------------------------------
__global__ __launch_bounds__(256) void epilogue_kernel(
    const float* __restrict__ x, float* __restrict__ out)
{
    const size_t base = (size_t)blockIdx.x * DDIM;
    const int t    = threadIdx.x;
    const int lane = t & 31;
    const int warp = t >> 5;

    __shared__ float red[8];

    float4 a  = *(const float4*)(out + base + t * 4);
    float4 xv = *(const float4*)(x   + base + t * 4);
    float y0 = a.x + xv.x, y1 = a.y + xv.y, y2 = a.z + xv.z, y3 = a.w + xv.w;

    float ss = y0 * y0 + y1 * y1 + y2 * y2 + y3 * y3;
    #pragma unroll
    for (int o = 16; o > 0; o >>= 1)
        ss += __shfl_xor_sync(0xffffffffu, ss, o);
    if (lane == 0) red[warp] = ss;
    __syncthreads();
    float tot = 0.0f;
    #pragma unroll
    for (int i = 0; i < 8; i++) tot += red[i];

    const float inv = 1.0f / sqrtf(tot);
    *(float4*)(out + base + t * 4) =
        make_float4(y0 * inv, y1 * inv, y2 * inv, y3 * inv);
}

// ---------------------------------------------------------------------------
// Launch
// ---------------------------------------------------------------------------
extern "C" void kernel_launch(void* const* d_in, const int* in_sizes, int n_in,
                              void* d_out, int out_size)
{
    const float* x  = (const float*)d_in[0];
    const float* Wq = (const float*)d_in[1];
    const float* Wk = (const float*)d_in[2];
    const float* Wv = (const float*)d_in[3];
    float* out = (float*)d_out;

    bf16 *xhi, *xlo, *Wqthi, *Wqtlo, *Wkthi, *Wktlo, *Wvhi, *Wvlo;
    bf16 *Mthi, *Mtlo, *zhi, *zlo, *Vthi, *Vtlo, *Phi, *Plo;
    float* Sc;
    cudaGetSymbolAddress((void**)&xhi,   g_xhi);    cudaGetSymbolAddress((void**)&xlo,   g_xlo);
    cudaGetSymbolAddress((void**)&Wqthi, g_Wqthi);  cudaGetSymbolAddress((void**)&Wqtlo, g_Wqtlo);
    cudaGetSymbolAddress((void**)&Wkthi, g_Wkthi);  cudaGetSymbolAddress((void**)&Wktlo, g_Wktlo);
    cudaGetSymbolAddress((void**)&Wvhi,  g_Wvhi);   cudaGetSymbolAddress((void**)&Wvlo,  g_Wvlo);
    cudaGetSymbolAddress((void**)&Mthi,  g_Mthi);   cudaGetSymbolAddress((void**)&Mtlo,  g_Mtlo);
    cudaGetSymbolAddress((void**)&zhi,   g_zhi);    cudaGetSymbolAddress((void**)&zlo,   g_zlo);
    cudaGetSymbolAddress((void**)&Vthi,  g_Vthi);   cudaGetSymbolAddress((void**)&Vtlo,  g_Vtlo);
    cudaGetSymbolAddress((void**)&Phi,   g_Phi);    cudaGetSymbolAddress((void**)&Plo,   g_Plo);
    cudaGetSymbolAddress((void**)&Sc,    g_S);

    cudaFuncSetAttribute(gemm_bf, cudaFuncAttributeMaxDynamicSharedMemorySize, SMEM_DYN);

    const size_t sQKV = (size_t)SLEN * DDIM;
    const size_t sSS  = (size_t)SLEN * SLEN;
    dim3 blk(256);

    // 0) split inputs: x and Wv elementwise; Wq/Wk transposed+split
    conv_split<<<(MTOT * DDIM) / 1024, blk>>>(x,  xhi, xlo);
    conv_split<<<(DDIM * DDIM) / 1024, blk>>>(Wv, Wvhi, Wvlo);
    dim3 gtr(DDIM / 32, DDIM / 32, 1);
    trans_split<<<gtr, blk>>>(Wq, Wqthi, Wqtlo);
    trans_split<<<gtr, blk>>>(Wk, Wkthi, Wktlo);

    // 1) Mt = Wkt · Wqtᵀ  (Mt[j,d] = M[d,j], M = Wqᵀ·Wk), bf16 hi/lo out
    dim3 gM(DDIM / 128, DDIM / 128, 1);      // (8, 8)
    gemm_bf<<<gM, blk, SMEM_DYN>>>(Wkthi, Wktlo, Wqthi, Wqtlo, nullptr, Mthi, Mtlo,
                                   DDIM, DDIM, DDIM, DDIM, 1, 0, 0, 0);

    // 2) z = x · Mtᵀ  (z[s,j] = sum_d x[s,d] M[d,j]), bf16 hi/lo out
    dim3 gz(DDIM / 128, MTOT / 128, 1);      // (8, 128)
    gemm_bf<<<gz, blk, SMEM_DYN>>>(xhi, xlo, Mthi, Mtlo, nullptr, zhi, zlo,
                                   DDIM, DDIM, DDIM, DDIM, 1, 0, 0, 0);

    // 3) Vt = Wv · xᵀ  (Vt[d,s] = V[s,d]), bf16 hi/lo out, coalesced
    dim3 gv(MTOT / 128, DDIM / 128, 1);      // (128, 8)
    gemm_bf<<<gv, blk, SMEM_DYN>>>(Wvhi, Wvlo, xhi, xlo, nullptr, Vthi, Vtlo,
                                   DDIM, DDIM, MTOT, DDIM, 1, 0, 0, 0);

    // 4) scores = z · xᵀ per batch (fp32 out)
    dim3 gsc(SLEN / 128, SLEN / 128, BATCH); // (32, 32, 4)
    gemm_bf<<<gsc, blk, SMEM_DYN>>>(zhi, zlo, xhi, xlo, Sc, nullptr, nullptr,
                                    DDIM, DDIM, SLEN, DDIM, 0, sQKV, sQKV, sSS);

    // 5) softmax -> P hi/lo (BETA = 1)
    softmax_split_kernel<<<MTOT, blk>>>(Sc, Phi, Plo);

    // 6) attended = P · Vtᵀ per batch (fp32 out into d_out)
    dim3 gav(DDIM / 128, SLEN / 128, BATCH); // (8, 32, 4)
    gemm_bf<<<gav, blk, SMEM_DYN>>>(Phi, Plo, Vthi, Vtlo, out, nullptr, nullptr,
                                    SLEN, MTOT, DDIM, SLEN, 0,
                                    sSS, (size_t)SLEN, sQKV);

    // 7) y = attended + x; L2 normalize
    epilogue_kernel<<<MTOT, blk>>>(x, out);
}

// round 11
// speedup vs baseline: 1.3413x; 1.1876x over previous
#include <cuda_runtime.h>
#include <cuda_bf16.h>
#include <cuda_fp16.h>
#include <cstdint>
#include <cstddef>

#define BATCH   4
#define SLEN    4096
#define DDIM    1024
#define MTOT    (BATCH * SLEN)          // 16384

typedef __nv_bfloat16  bf16;
typedef __nv_bfloat162 bf162;

// ---------------------------------------------------------------------------
// Scratch (allocation-free rule: __device__ globals).
// Scores path (bf16 3-pass):  scores = z·xᵀ, z = x·M, M = Wqᵀ·Wk
// PV path (fp16 2-pass):      Vᵀ = Wv·xᵀ (fp16), attended = P·Vᵀᵀ
// ---------------------------------------------------------------------------
__device__ bf16 g_xhi [(size_t)MTOT * DDIM];
__device__ bf16 g_xlo [(size_t)MTOT * DDIM];
__device__ bf16 g_Wqthi[(size_t)DDIM * DDIM];
__device__ bf16 g_Wqtlo[(size_t)DDIM * DDIM];
__device__ bf16 g_Wkthi[(size_t)DDIM * DDIM];
__device__ bf16 g_Wktlo[(size_t)DDIM * DDIM];
__device__ bf16 g_Mthi[(size_t)DDIM * DDIM];
__device__ bf16 g_Mtlo[(size_t)DDIM * DDIM];
__device__ bf16 g_zhi [(size_t)MTOT * DDIM];
__device__ bf16 g_zlo [(size_t)MTOT * DDIM];
__device__ float g_S  [(size_t)MTOT * SLEN];
// fp16 path
__device__ __half g_x16 [(size_t)MTOT * DDIM];   // x rounded to fp16
__device__ __half g_Wvh [(size_t)DDIM * DDIM];   // Wv split fp16
__device__ __half g_Wvl [(size_t)DDIM * DDIM];
__device__ __half g_Vt16[(size_t)DDIM * MTOT];   // Vᵀ fp16 [D, MTOT]
__device__ __half g_Ph  [(size_t)MTOT * SLEN];   // P split fp16
__device__ __half g_Pl  [(size_t)MTOT * SLEN];

// ---------------------------------------------------------------------------
// Helpers (arch-agnostic PTX only: plain sm_103 target)
// ---------------------------------------------------------------------------
__device__ __forceinline__ uint32_t smem_u32(const void* p) {
    uint32_t a;
    asm("{ .reg .u64 t; cvta.to.shared.u64 t, %1; cvt.u32.u64 %0, t; }" : "=r"(a) : "l"(p));
    return a;
}
__device__ __forceinline__ void ldsm4(uint32_t& r0, uint32_t& r1, uint32_t& r2, uint32_t& r3,
                                      uint32_t addr) {
    asm volatile("ldmatrix.sync.aligned.m8n8.x4.shared.b16 {%0,%1,%2,%3}, [%4];"
                 : "=r"(r0), "=r"(r1), "=r"(r2), "=r"(r3) : "r"(addr));
}
__device__ __forceinline__ void mma16816(float* c, const uint32_t* a, const uint32_t* b) {
    asm volatile(
        "mma.sync.aligned.m16n8k16.row.col.f32.bf16.bf16.f32 "
        "{%0,%1,%2,%3}, {%4,%5,%6,%7}, {%8,%9}, {%0,%1,%2,%3};"
        : "+f"(c[0]), "+f"(c[1]), "+f"(c[2]), "+f"(c[3])
        : "r"(a[0]), "r"(a[1]), "r"(a[2]), "r"(a[3]), "r"(b[0]), "r"(b[1]));
}
__device__ __forceinline__ void mma16816h(float* c, const uint32_t* a, const uint32_t* b) {
    asm volatile(
        "mma.sync.aligned.m16n8k16.row.col.f32.f16.f16.f32 "
        "{%0,%1,%2,%3}, {%4,%5,%6,%7}, {%8,%9}, {%0,%1,%2,%3};"
        : "+f"(c[0]), "+f"(c[1]), "+f"(c[2]), "+f"(c[3])
        : "r"(a[0]), "r"(a[1]), "r"(a[2]), "r"(a[3]), "r"(b[0]), "r"(b[1]));
}
__device__ __forceinline__ void cpasync16(uint32_t dst, const void* src) {
    asm volatile("cp.async.cg.shared.global [%0], [%1], 16;" :: "r"(dst), "l"(src));
}
__device__ __forceinline__ void split2(float x, float y, bf162& h, bf162& l) {
    h = __floats2bfloat162_rn(x, y);
    float2 f = __bfloat1622float2(h);
    l = __floats2bfloat162_rn(x - f.x, y - f.y);
}

// ---------------------------------------------------------------------------
// Conversion kernels
// ---------------------------------------------------------------------------
__global__ __launch_bounds__(256) void conv_split(
    const float* __restrict__ src, bf16* __restrict__ hi, bf16* __restrict__ lo)
{
    size_t i = ((size_t)blockIdx.x * 256 + threadIdx.x) * 4;
    float4 v = *(const float4*)(src + i);
    bf162 h0, l0, h1, l1;
    split2(v.x, v.y, h0, l0);
    split2(v.z, v.w, h1, l1);
    *(bf162*)(hi + i)     = h0;
    *(bf162*)(hi + i + 2) = h1;
    *(bf162*)(lo + i)     = l0;
    *(bf162*)(lo + i + 2) = l1;
}

__global__ __launch_bounds__(256) void conv_round16(
    const float* __restrict__ src, __half* __restrict__ dst)
{
    size_t i = ((size_t)blockIdx.x * 256 + threadIdx.x) * 4;
    float4 v = *(const float4*)(src + i);
    *(__half2*)(dst + i)     = __floats2half2_rn(v.x, v.y);
    *(__half2*)(dst + i + 2) = __floats2half2_rn(v.z, v.w);
}

__global__ __launch_bounds__(256) void conv_split16(
    const float* __restrict__ src, __half* __restrict__ hi, __half* __restrict__ lo)
{
    size_t i = ((size_t)blockIdx.x * 256 + threadIdx.x) * 4;
    float4 v = *(const float4*)(src + i);
    __half2 h0 = __floats2half2_rn(v.x, v.y);
    __half2 h1 = __floats2half2_rn(v.z, v.w);
    float2 f0 = __half22float2(h0);
    float2 f1 = __half22float2(h1);
    *(__half2*)(hi + i)     = h0;
    *(__half2*)(hi + i + 2) = h1;
    *(__half2*)(lo + i)     = __floats2half2_rn(v.x - f0.x, v.y - f0.y);
    *(__half2*)(lo + i + 2) = __floats2half2_rn(v.z - f1.x, v.w - f1.y);
}

// Transpose + split: out[i,e] = src[e,i] for 1024x1024 fp32, bf16 hi/lo out.
__global__ __launch_bounds__(256) void trans_split(
    const float* __restrict__ src, bf16* __restrict__ hi, bf16* __restrict__ lo)
{
    __shared__ float t[32][33];
    const int tx = threadIdx.x & 31;
    const int ty = threadIdx.x >> 5;
    const int bx = blockIdx.x * 32;
    const int by = blockIdx.y * 32;
    #pragma unroll
    for (int i = 0; i < 4; i++)
        t[ty + i * 8][tx] = src[(size_t)(by + ty + i * 8) * DDIM + bx + tx];
    __syncthreads();
    #pragma unroll
    for (int i = 0; i < 4; i++) {
        const int r = ty + i * 8;
        float v = t[tx][r];
        bf16 h = __float2bfloat16_rn(v);
        bf16 l = __float2bfloat16_rn(v - __bfloat162float(h));
        hi[(size_t)(bx + r) * DDIM + by + tx] = h;
        lo[(size_t)(bx + r) * DDIM + by + tx] = l;
    }
}

// ---------------------------------------------------------------------------
// bf16 NT GEMM, 3-pass fp32 emulation (scores path). 128x128, KC=32,
// 2-stage cp.async, 2 CTAs/SM. mode 0: fp32 C. mode 1: bf16 hi/lo out.
// ---------------------------------------------------------------------------
#define KC       32
#define LDT      40
#define MAT_B    (128 * LDT * 2)            // 10240 B
#define STAGE_B  (4 * MAT_B)                // 40960 B
#define SMEM_DYN (2 * STAGE_B)              // 81920 B

__global__ __launch_bounds__(256, 2) void gemm_bf(
    const bf16* __restrict__ Ahi, const bf16* __restrict__ Alo,
    const bf16* __restrict__ Bhi, const bf16* __restrict__ Blo,
    float* __restrict__ Cf, bf16* __restrict__ Chi, bf16* __restrict__ Clo,
    int lda, int ldb, int ldc, int K, int mode,
    size_t sA, size_t sB, size_t sC)
{
    extern __shared__ char smem[];
    Ahi += (size_t)blockIdx.z * sA;  Alo += (size_t)blockIdx.z * sA;
    Bhi += (size_t)blockIdx.z * sB;  Blo += (size_t)blockIdx.z * sB;

    const int tid  = threadIdx.x;
    const int lane = tid & 31;
    const int wid  = tid >> 5;
    const int bm   = blockIdx.y * 128;
    const int bn   = blockIdx.x * 128;
    const int m_warp = (wid & 3) * 32;
    const int n_warp = (wid >> 2) * 64;

    const uint32_t sbase = smem_u32(smem);
    const uint32_t aoff = (uint32_t)((m_warp + (lane & 15)) * (LDT * 2) + ((lane >> 4) * 8) * 2);
    const uint32_t boff = (uint32_t)((n_warp + (lane & 7) + ((lane & 16) ? 8 : 0)) * (LDT * 2)
                                     + ((lane & 8) ? 8 : 0) * 2);

    float acc[2][8][4];
    #pragma unroll
    for (int t = 0; t < 2; t++)
        #pragma unroll
        for (int n = 0; n < 8; n++)
            #pragma unroll
            for (int q = 0; q < 4; q++) acc[t][n][q] = 0.0f;

    const int nk = K / KC;

    auto issue = [&](int buf, int c) {
        const int k0 = c * KC;
        const uint32_t sb = sbase + buf * STAGE_B;
        #pragma unroll
        for (int i = 0; i < 2; i++) {
            const int l   = tid + i * 256;
            const int row = l >> 2;
            const int ch  = (l & 3) * 16;
            const uint32_t soff = (uint32_t)(row * (LDT * 2)) + ch;
            const size_t ga = (size_t)(bm + row) * lda + k0;
            const size_t gb = (size_t)(bn + row) * ldb + k0;
            cpasync16(sb + 0 * MAT_B + soff, (const char*)(Ahi + ga) + ch);
            cpasync16(sb + 1 * MAT_B + soff, (const char*)(Alo + ga) + ch);
            cpasync16(sb + 2 * MAT_B + soff, (const char*)(Bhi + gb) + ch);
            cpasync16(sb + 3 * MAT_B + soff, (const char*)(Blo + gb) + ch);
        }
    };

    auto compute = [&](int buf) {
        const uint32_t base = sbase + buf * STAGE_B;
        #pragma unroll
        for (int ks = 0; ks < 2; ks++) {
            const uint32_t kb = (uint32_t)ks * 32;
            uint32_t bh[4][4], bl[4][4];
            #pragma unroll
            for (int u = 0; u < 4; u++) {
                ldsm4(bh[u][0], bh[u][1], bh[u][2], bh[u][3],
                      base + 2 * MAT_B + boff + u * (16 * LDT * 2) + kb);
                ldsm4(bl[u][0], bl[u][1], bl[u][2], bl[u][3],
                      base + 3 * MAT_B + boff + u * (16 * LDT * 2) + kb);
            }
            #pragma unroll
            for (int t = 0; t < 2; t++) {
                uint32_t ah[4], al[4];
                ldsm4(ah[0], ah[1], ah[2], ah[3],
                      base + 0 * MAT_B + aoff + t * (16 * LDT * 2) + kb);
                ldsm4(al[0], al[1], al[2], al[3],
                      base + 1 * MAT_B + aoff + t * (16 * LDT * 2) + kb);
                #pragma unroll
                for (int n = 0; n < 8; n++)
                    mma16816(acc[t][n], ah, &bh[n >> 1][(n & 1) * 2]);
                #pragma unroll
                for (int n = 0; n < 8; n++)
                    mma16816(acc[t][n], ah, &bl[n >> 1][(n & 1) * 2]);
                #pragma unroll
                for (int n = 0; n < 8; n++)
                    mma16816(acc[t][n], al, &bh[n >> 1][(n & 1) * 2]);
            }
        }
    };

    issue(0, 0);
    asm volatile("cp.async.commit_group;" ::: "memory");

    for (int c = 0; c < nk; ++c) {
        asm volatile("cp.async.wait_group 0;" ::: "memory");
        __syncthreads();
        if (c + 1 < nk) {
            issue((c + 1) & 1, c + 1);
            asm volatile("cp.async.commit_group;" ::: "memory");
        }
        compute(c & 1);
    }

    #pragma unroll
    for (int t = 0; t < 2; t++)
        #pragma unroll
        for (int n = 0; n < 8; n++) {
            const int row = bm + m_warp + t * 16 + (lane >> 2);
            const int col = bn + n_warp + n * 8 + (lane & 3) * 2;
            if (mode == 0) {
                float* C0 = Cf + (size_t)blockIdx.z * sC;
                *(float2*)(C0 + (size_t)row * ldc + col) =
                    make_float2(acc[t][n][0], acc[t][n][1]);
                *(float2*)(C0 + (size_t)(row + 8) * ldc + col) =
                    make_float2(acc[t][n][2], acc[t][n][3]);
            } else {
                bf162 h, l;
                split2(acc[t][n][0], acc[t][n][1], h, l);
                *(bf162*)(Chi + (size_t)row * ldc + col) = h;
                *(bf162*)(Clo + (size_t)row * ldc + col) = l;
                split2(acc[t][n][2], acc[t][n][3], h, l);
                *(bf162*)(Chi + (size_t)(row + 8) * ldc + col) = h;
                *(bf162*)(Clo + (size_t)(row + 8) * ldc + col) = l;
            }
        }
}

// ---------------------------------------------------------------------------
// fp16 NT GEMM, 2-pass (A split fp16, B rounded fp16): C = sum_k A[m,k]*B[n,k]
// error ~2^-12 relative (B rounding only). 128x128, KC=32, 2 CTAs/SM.
// mode 0: fp32 C.  mode 3: fp16 rounded C.
// ---------------------------------------------------------------------------
#define H2_STAGE (3 * MAT_B)                // Ah, Al, Bh = 30720 B
#define H2_SMEM  (2 * H2_STAGE)             // 61440 B

__global__ __launch_bounds__(256, 2) void gemm_h2(
    const __half* __restrict__ Ah, const __half* __restrict__ Al,
    const __half* __restrict__ Bh,
    float* __restrict__ Cf, __half* __restrict__ C16,
    int lda, int ldb, int ldc, int K, int mode,
    size_t sA, size_t sB, size_t sC)
{
    extern __shared__ char smem[];
    Ah += (size_t)blockIdx.z * sA;  Al += (size_t)blockIdx.z * sA;
    Bh += (size_t)blockIdx.z * sB;

    const int tid  = threadIdx.x;
    const int lane = tid & 31;
    const int wid  = tid >> 5;
    const int bm   = blockIdx.y * 128;
    const int bn   = blockIdx.x * 128;
    const int m_warp = (wid & 3) * 32;
    const int n_warp = (wid >> 2) * 64;

    const uint32_t sbase = smem_u32(smem);
    const uint32_t aoff = (uint32_t)((m_warp + (lane & 15)) * (LDT * 2) + ((lane >> 4) * 8) * 2);
    const uint32_t boff = (uint32_t)((n_warp + (lane & 7) + ((lane & 16) ? 8 : 0)) * (LDT * 2)
                                     + ((lane & 8) ? 8 : 0) * 2);

    float acc[2][8][4];
    #pragma unroll
    for (int t = 0; t < 2; t++)
        #pragma unroll
        for (int n = 0; n < 8; n++)
            #pragma unroll
            for (int q = 0; q < 4; q++) acc[t][n][q] = 0.0f;

    const int nk = K / KC;

    auto issue = [&](int buf, int c) {
        const int k0 = c * KC;
        const uint32_t sb = sbase + buf * H2_STAGE;
        #pragma unroll
        for (int i = 0; i < 2; i++) {
            const int l   = tid + i * 256;
            const int row = l >> 2;
            const int ch  = (l & 3) * 16;
            const uint32_t soff = (uint32_t)(row * (LDT * 2)) + ch;
            const size_t ga = (size_t)(bm + row) * lda + k0;
            const size_t gb = (size_t)(bn + row) * ldb + k0;
            cpasync16(sb + 0 * MAT_B + soff, (const char*)(Ah + ga) + ch);
            cpasync16(sb + 1 * MAT_B + soff, (const char*)(Al + ga) + ch);
            cpasync16(sb + 2 * MAT_B + soff, (const char*)(Bh + gb) + ch);
        }
    };

    auto compute = [&](int buf) {
        const uint32_t base = sbase + buf * H2_STAGE;
        #pragma unroll
        for (int ks = 0; ks < 2; ks++) {
            const uint32_t kb = (uint32_t)ks * 32;
            uint32_t bh[4][4];
            #pragma unroll
            for (int u = 0; u < 4; u++)
                ldsm4(bh[u][0], bh[u][1], bh[u][2], bh[u][3],
                      base + 2 * MAT_B + boff + u * (16 * LDT * 2) + kb);
            #pragma unroll
            for (int t = 0; t < 2; t++) {
                uint32_t ah[4], al[4];
                ldsm4(ah[0], ah[1], ah[2], ah[3],
                      base + 0 * MAT_B + aoff + t * (16 * LDT * 2) + kb);
                ldsm4(al[0], al[1], al[2], al[3],
                      base + 1 * MAT_B + aoff + t * (16 * LDT * 2) + kb);
                #pragma unroll
                for (int n = 0; n < 8; n++)
                    mma16816h(acc[t][n], ah, &bh[n >> 1][(n & 1) * 2]);
                #pragma unroll
                for (int n = 0; n < 8; n++)
                    mma16816h(acc[t][n], al, &bh[n >> 1][(n & 1) * 2]);
            }
        }
    };

    issue(0, 0);
    asm volatile("cp.async.commit_group;" ::: "memory");

    for (int c = 0; c < nk; ++c) {
        asm volatile("cp.async.wait_group 0;" ::: "memory");
        __syncthreads();
        if (c + 1 < nk) {
            issue((c + 1) & 1, c + 1);
            asm volatile("cp.async.commit_group;" ::: "memory");
        }
        compute(c & 1);
    }

    #pragma unroll
    for (int t = 0; t < 2; t++)
        #pragma unroll
        for (int n = 0; n < 8; n++) {
            const int row = bm + m_warp + t * 16 + (lane >> 2);
            const int col = bn + n_warp + n * 8 + (lane & 3) * 2;
            if (mode == 0) {
                float* C0 = Cf + (size_t)blockIdx.z * sC;
                *(float2*)(C0 + (size_t)row * ldc + col) =
                    make_float2(acc[t][n][0], acc[t][n][1]);
                *(float2*)(C0 + (size_t)(row + 8) * ldc + col) =
                    make_float2(acc[t][n][2], acc[t][n][3]);
            } else {
                *(__half2*)(C16 + (size_t)row * ldc + col) =
                    __floats2half2_rn(acc[t][n][0], acc[t][n][1]);
                *(__half2*)(C16 + (size_t)(row + 8) * ldc + col) =
                    __floats2half2_rn(acc[t][n][2], acc[t][n][3]);
            }
        }
}

// ---------------------------------------------------------------------------
// Row softmax over 4096 fp32 scores -> fp16 hi/lo probabilities.
// ---------------------------------------------------------------------------
__global__ __launch_bounds__(256) void softmax_split_kernel(
    const float* __restrict__ Sm, __half* __restrict__ Ph, __half* __restrict__ Pl)
{
    const float* row = Sm + (size_t)blockIdx.x * SLEN;
    __half* ph = Ph + (size_t)blockIdx.x * SLEN;
    __half* pl = Pl + (size_t)blockIdx.x * SLEN;
    const int t    = threadIdx.x;
    const int lane = t & 31;
    const int warp = t >> 5;

    __shared__ float red[8];

    float v[16];
    float mx = -1e30f;
    #pragma unroll
    for (int i = 0; i < 16; i++) {
        v[i] = row[t + (i << 8)];
        mx = fmaxf(mx, v[i]);
    }
    #pragma unroll
    for (int o = 16; o > 0; o >>= 1)
        mx = fmaxf(mx, __shfl_xor_sync(0xffffffffu, mx, o));
    if (lane == 0) red[warp] = mx;
    __syncthreads();
    float rmax = red[0];
    #pragma unroll
    for (int i = 1; i < 8; i++) rmax = fmaxf(rmax, red[i]);

    float sum = 0.0f;
    #pragma unroll
    for (int i = 0; i < 16; i++) {
        v[i] = __expf(v[i] - rmax);
        sum += v[i];
    }
    #pragma unroll
    for (int o = 16; o > 0; o >>= 1)
        sum += __shfl_xor_sync(0xffffffffu, sum, o);
    __syncthreads();
    if (lane == 0) red[warp] = sum;
    __syncthreads();
    float rsum = 0.0f;
    #pragma unroll
    for (int i = 0; i < 8; i++) rsum += red[i];

    const float inv = 1.0f / rsum;
    #pragma unroll
    for (int i = 0; i < 16; i++) {
        float p = v[i] * inv;
        __half h = __float2half_rn(p);
        ph[t + (i << 8)] = h;
        pl[t + (i << 8)] = __float2half_rn(p - __half2float(h));
    }
}

// ---------------------------------------------------------------------------
// Final epilogue: y = attended + x;  out = y / ||y||_2 per 1024-row.
// ---------------------------------------------------------------------------
__global__ __launch_bounds__(256) void epilogue_kernel(
    const float* __restrict__ x, float* __restrict__ out)
{
    const size_t base = (size_t)blockIdx.x * DDIM;
    const int t    = threadIdx.x;
    const int lane = t & 31;
    const int warp = t >> 5;

    __shared__ float red[8];

    float4 a  = *(const float4*)(out + base + t * 4);
    float4 xv = *(const float4*)(x   + base + t * 4);
    float y0 = a.x + xv.x, y1 = a.y + xv.y, y2 = a.z + xv.z, y3 = a.w + xv.w;

    float ss = y0 * y0 + y1 * y1 + y2 * y2 + y3 * y3;
    #pragma unroll
    for (int o = 16; o > 0; o >>= 1)
        ss += __shfl_xor_sync(0xffffffffu, ss, o);
    if (lane == 0) red[warp] = ss;
    __syncthreads();
    float tot = 0.0f;
    #pragma unroll
    for (int i = 0; i < 8; i++) tot += red[i];

    const float inv = 1.0f / sqrtf(tot);
    *(float4*)(out + base + t * 4) =
        make_float4(y0 * inv, y1 * inv, y2 * inv, y3 * inv);
}

// ---------------------------------------------------------------------------
// Launch
// ---------------------------------------------------------------------------
extern "C" void kernel_launch(void* const* d_in, const int* in_sizes, int n_in,
                              void* d_out, int out_size)
{
    const float* x  = (const float*)d_in[0];
    const float* Wq = (const float*)d_in[1];
    const float* Wk = (const float*)d_in[2];
    const float* Wv = (const float*)d_in[3];
    float* out = (float*)d_out;

    bf16 *xhi, *xlo, *Wqthi, *Wqtlo, *Wkthi, *Wktlo, *Mthi, *Mtlo, *zhi, *zlo;
    __half *x16, *Wvh, *Wvl, *Vt16, *Ph, *Pl;
    float* Sc;
    cudaGetSymbolAddress((void**)&xhi,   g_xhi);    cudaGetSymbolAddress((void**)&xlo,   g_xlo);
    cudaGetSymbolAddress((void**)&Wqthi, g_Wqthi);  cudaGetSymbolAddress((void**)&Wqtlo, g_Wqtlo);
    cudaGetSymbolAddress((void**)&Wkthi, g_Wkthi);  cudaGetSymbolAddress((void**)&Wktlo, g_Wktlo);
    cudaGetSymbolAddress((void**)&Mthi,  g_Mthi);   cudaGetSymbolAddress((void**)&Mtlo,  g_Mtlo);
    cudaGetSymbolAddress((void**)&zhi,   g_zhi);    cudaGetSymbolAddress((void**)&zlo,   g_zlo);
    cudaGetSymbolAddress((void**)&x16,   g_x16);
    cudaGetSymbolAddress((void**)&Wvh,   g_Wvh);    cudaGetSymbolAddress((void**)&Wvl,   g_Wvl);
    cudaGetSymbolAddress((void**)&Vt16,  g_Vt16);
    cudaGetSymbolAddress((void**)&Ph,    g_Ph);     cudaGetSymbolAddress((void**)&Pl,    g_Pl);
    cudaGetSymbolAddress((void**)&Sc,    g_S);

    cudaFuncSetAttribute(gemm_bf, cudaFuncAttributeMaxDynamicSharedMemorySize, SMEM_DYN);
    cudaFuncSetAttribute(gemm_h2, cudaFuncAttributeMaxDynamicSharedMemorySize, H2_SMEM);

    const size_t sQKV = (size_t)SLEN * DDIM;
    const size_t sSS  = (size_t)SLEN * SLEN;
    dim3 blk(256);

    // 0) conversions
    conv_split<<<(MTOT * DDIM) / 1024, blk>>>(x, xhi, xlo);
    conv_round16<<<(MTOT * DDIM) / 1024, blk>>>(x, x16);
    conv_split16<<<(DDIM * DDIM) / 1024, blk>>>(Wv, Wvh, Wvl);
    dim3 gtr(DDIM / 32, DDIM / 32, 1);
    trans_split<<<gtr, blk>>>(Wq, Wqthi, Wqtlo);
    trans_split<<<gtr, blk>>>(Wk, Wkthi, Wktlo);

    // 1) Mt = Wkt · Wqtᵀ  (bf16 3-pass)
    dim3 gM(DDIM / 128, DDIM / 128, 1);
    gemm_bf<<<gM, blk, SMEM_DYN>>>(Wkthi, Wktlo, Wqthi, Wqtlo, nullptr, Mthi, Mtlo,
                                   DDIM, DDIM, DDIM, DDIM, 1, 0, 0, 0);

    // 2) z = x · Mtᵀ  (bf16 3-pass)
    dim3 gz(DDIM / 128, MTOT / 128, 1);
    gemm_bf<<<gz, blk, SMEM_DYN>>>(xhi, xlo, Mthi, Mtlo, nullptr, zhi, zlo,
                                   DDIM, DDIM, DDIM, DDIM, 1, 0, 0, 0);

    // 3) Vt = Wv · xᵀ  (fp16 2-pass, fp16 out, coalesced)
    dim3 gv(MTOT / 128, DDIM / 128, 1);
    gemm_h2<<<gv, blk, H2_SMEM>>>(Wvh, Wvl, x16, nullptr, Vt16,
                                  DDIM, DDIM, MTOT, DDIM, 3, 0, 0, 0);

    // 4) scores = z · xᵀ per batch (bf16 3-pass, fp32 out)
    dim3 gsc(SLEN / 128, SLEN / 128, BATCH);
    gemm_bf<<<gsc, blk, SMEM_DYN>>>(zhi, zlo, xhi, xlo, Sc, nullptr, nullptr,
                                    DDIM, DDIM, SLEN, DDIM, 0, sQKV, sQKV, sSS);

    // 5) softmax -> P fp16 hi/lo (BETA = 1)
    softmax_split_kernel<<<MTOT, blk>>>(Sc, Ph, Pl);

    // 6) attended = P · Vtᵀ per batch (fp16 2-pass, fp32 out into d_out)
    dim3 gav(DDIM / 128, SLEN / 128, BATCH);
    gemm_h2<<<gav, blk, H2_SMEM>>>(Ph, Pl, Vt16, out, nullptr,
                                   SLEN, MTOT, DDIM, SLEN, 0,
                                   sSS, (size_t)SLEN, sQKV);

    // 7) y = attended + x; L2 normalize
    epilogue_kernel<<<MTOT, blk>>>(x, out);
}

// round 12
// speedup vs baseline: 1.5810x; 1.1787x over previous
#include <cuda_runtime.h>
#include <cuda_bf16.h>
#include <cuda_fp16.h>
#include <cstdint>
#include <cstddef>

#define BATCH   4
#define SLEN    4096
#define DDIM    1024
#define MTOT    (BATCH * SLEN)          // 16384

typedef __nv_bfloat16  bf16;
typedef __nv_bfloat162 bf162;

// ---------------------------------------------------------------------------
// Scratch (allocation-free rule: __device__ globals).
// z path (bf16 3-pass):   z = x·M, M = Wqᵀ·Wk           (K projection gone)
// scores (fp16 2-pass):   scores = (zh+zl)·x16ᵀ          (err: x rounding 2^-12)
// PV path (fp16 2-pass):  Vᵀ = Wv·xᵀ, attended = P·Vᵀᵀ   (err: V rounding)
// ---------------------------------------------------------------------------
__device__ bf16 g_xhi [(size_t)MTOT * DDIM];
__device__ bf16 g_xlo [(size_t)MTOT * DDIM];
__device__ bf16 g_Wqthi[(size_t)DDIM * DDIM];
__device__ bf16 g_Wqtlo[(size_t)DDIM * DDIM];
__device__ bf16 g_Wkthi[(size_t)DDIM * DDIM];
__device__ bf16 g_Wktlo[(size_t)DDIM * DDIM];
__device__ bf16 g_Mthi[(size_t)DDIM * DDIM];
__device__ bf16 g_Mtlo[(size_t)DDIM * DDIM];
__device__ float g_S  [(size_t)MTOT * SLEN];
// fp16 operands
__device__ __half g_x16 [(size_t)MTOT * DDIM];   // x rounded to fp16
__device__ __half g_zh16[(size_t)MTOT * DDIM];   // z split fp16
__device__ __half g_zl16[(size_t)MTOT * DDIM];
__device__ __half g_Wvh [(size_t)DDIM * DDIM];   // Wv split fp16
__device__ __half g_Wvl [(size_t)DDIM * DDIM];
__device__ __half g_Vt16[(size_t)DDIM * MTOT];   // Vᵀ fp16 [D, MTOT]
__device__ __half g_Ph  [(size_t)MTOT * SLEN];   // P split fp16
__device__ __half g_Pl  [(size_t)MTOT * SLEN];

// ---------------------------------------------------------------------------
// Helpers (arch-agnostic PTX only: plain sm_103 target)
// ---------------------------------------------------------------------------
__device__ __forceinline__ uint32_t smem_u32(const void* p) {
    uint32_t a;
    asm("{ .reg .u64 t; cvta.to.shared.u64 t, %1; cvt.u32.u64 %0, t; }" : "=r"(a) : "l"(p));
    return a;
}
__device__ __forceinline__ void ldsm4(uint32_t& r0, uint32_t& r1, uint32_t& r2, uint32_t& r3,
                                      uint32_t addr) {
    asm volatile("ldmatrix.sync.aligned.m8n8.x4.shared.b16 {%0,%1,%2,%3}, [%4];"
                 : "=r"(r0), "=r"(r1), "=r"(r2), "=r"(r3) : "r"(addr));
}
__device__ __forceinline__ void mma16816(float* c, const uint32_t* a, const uint32_t* b) {
    asm volatile(
        "mma.sync.aligned.m16n8k16.row.col.f32.bf16.bf16.f32 "
        "{%0,%1,%2,%3}, {%4,%5,%6,%7}, {%8,%9}, {%0,%1,%2,%3};"
        : "+f"(c[0]), "+f"(c[1]), "+f"(c[2]), "+f"(c[3])
        : "r"(a[0]), "r"(a[1]), "r"(a[2]), "r"(a[3]), "r"(b[0]), "r"(b[1]));
}
__device__ __forceinline__ void mma16816h(float* c, const uint32_t* a, const uint32_t* b) {
    asm volatile(
        "mma.sync.aligned.m16n8k16.row.col.f32.f16.f16.f32 "
        "{%0,%1,%2,%3}, {%4,%5,%6,%7}, {%8,%9}, {%0,%1,%2,%3};"
        : "+f"(c[0]), "+f"(c[1]), "+f"(c[2]), "+f"(c[3])
        : "r"(a[0]), "r"(a[1]), "r"(a[2]), "r"(a[3]), "r"(b[0]), "r"(b[1]));
}
__device__ __forceinline__ void cpasync16(uint32_t dst, const void* src) {
    asm volatile("cp.async.cg.shared.global [%0], [%1], 16;" :: "r"(dst), "l"(src));
}
__device__ __forceinline__ void split2(float x, float y, bf162& h, bf162& l) {
    h = __floats2bfloat162_rn(x, y);
    float2 f = __bfloat1622float2(h);
    l = __floats2bfloat162_rn(x - f.x, y - f.y);
}
__device__ __forceinline__ void split2h(float x, float y, __half2& h, __half2& l) {
    h = __floats2half2_rn(x, y);
    float2 f = __half22float2(h);
    l = __floats2half2_rn(x - f.x, y - f.y);
}

// ---------------------------------------------------------------------------
// Conversion kernels
// ---------------------------------------------------------------------------
__global__ __launch_bounds__(256) void conv_split(
    const float* __restrict__ src, bf16* __restrict__ hi, bf16* __restrict__ lo)
{
    size_t i = ((size_t)blockIdx.x * 256 + threadIdx.x) * 4;
    float4 v = *(const float4*)(src + i);
    bf162 h0, l0, h1, l1;
    split2(v.x, v.y, h0, l0);
    split2(v.z, v.w, h1, l1);
    *(bf162*)(hi + i)     = h0;
    *(bf162*)(hi + i + 2) = h1;
    *(bf162*)(lo + i)     = l0;
    *(bf162*)(lo + i + 2) = l1;
}

__global__ __launch_bounds__(256) void conv_round16(
    const float* __restrict__ src, __half* __restrict__ dst)
{
    size_t i = ((size_t)blockIdx.x * 256 + threadIdx.x) * 4;
    float4 v = *(const float4*)(src + i);
    *(__half2*)(dst + i)     = __floats2half2_rn(v.x, v.y);
    *(__half2*)(dst + i + 2) = __floats2half2_rn(v.z, v.w);
}

__global__ __launch_bounds__(256) void conv_split16(
    const float* __restrict__ src, __half* __restrict__ hi, __half* __restrict__ lo)
{
    size_t i = ((size_t)blockIdx.x * 256 + threadIdx.x) * 4;
    float4 v = *(const float4*)(src + i);
    __half2 h0, l0, h1, l1;
    split2h(v.x, v.y, h0, l0);
    split2h(v.z, v.w, h1, l1);
    *(__half2*)(hi + i)     = h0;
    *(__half2*)(hi + i + 2) = h1;
    *(__half2*)(lo + i)     = l0;
    *(__half2*)(lo + i + 2) = l1;
}

// Transpose + split: out[i,e] = src[e,i] for 1024x1024 fp32, bf16 hi/lo out.
__global__ __launch_bounds__(256) void trans_split(
    const float* __restrict__ src, bf16* __restrict__ hi, bf16* __restrict__ lo)
{
    __shared__ float t[32][33];
    const int tx = threadIdx.x & 31;
    const int ty = threadIdx.x >> 5;
    const int bx = blockIdx.x * 32;
    const int by = blockIdx.y * 32;
    #pragma unroll
    for (int i = 0; i < 4; i++)
        t[ty + i * 8][tx] = src[(size_t)(by + ty + i * 8) * DDIM + bx + tx];
    __syncthreads();
    #pragma unroll
    for (int i = 0; i < 4; i++) {
        const int r = ty + i * 8;
        float v = t[tx][r];
        bf16 h = __float2bfloat16_rn(v);
        bf16 l = __float2bfloat16_rn(v - __bfloat162float(h));
        hi[(size_t)(bx + r) * DDIM + by + tx] = h;
        lo[(size_t)(bx + r) * DDIM + by + tx] = l;
    }
}

// ---------------------------------------------------------------------------
// bf16 NT GEMM, 3-pass fp32 emulation. 128x128, KC=32, 2-stage cp.async,
// 2 CTAs/SM. mode 0: fp32 C. mode 1: bf16 hi/lo out. mode 4: fp16 hi/lo out.
// ---------------------------------------------------------------------------
#define KC       32
#define LDT      40
#define MAT_B    (128 * LDT * 2)            // 10240 B
#define STAGE_B  (4 * MAT_B)                // 40960 B
#define SMEM_DYN (2 * STAGE_B)              // 81920 B

__global__ __launch_bounds__(256, 2) void gemm_bf(
    const bf16* __restrict__ Ahi, const bf16* __restrict__ Alo,
    const bf16* __restrict__ Bhi, const bf16* __restrict__ Blo,
    float* __restrict__ Cf, bf16* __restrict__ Chi, bf16* __restrict__ Clo,
    int lda, int ldb, int ldc, int K, int mode,
    size_t sA, size_t sB, size_t sC)
{
    extern __shared__ char smem[];
    Ahi += (size_t)blockIdx.z * sA;  Alo += (size_t)blockIdx.z * sA;
    Bhi += (size_t)blockIdx.z * sB;  Blo += (size_t)blockIdx.z * sB;

    const int tid  = threadIdx.x;
    const int lane = tid & 31;
    const int wid  = tid >> 5;
    const int bm   = blockIdx.y * 128;
    const int bn   = blockIdx.x * 128;
    const int m_warp = (wid & 3) * 32;
    const int n_warp = (wid >> 2) * 64;

    const uint32_t sbase = smem_u32(smem);
    const uint32_t aoff = (uint32_t)((m_warp + (lane & 15)) * (LDT * 2) + ((lane >> 4) * 8) * 2);
    const uint32_t boff = (uint32_t)((n_warp + (lane & 7) + ((lane & 16) ? 8 : 0)) * (LDT * 2)
                                     + ((lane & 8) ? 8 : 0) * 2);

    float acc[2][8][4];
    #pragma unroll
    for (int t = 0; t < 2; t++)
        #pragma unroll
        for (int n = 0; n < 8; n++)
            #pragma unroll
            for (int q = 0; q < 4; q++) acc[t][n][q] = 0.0f;

    const int nk = K / KC;

    auto issue = [&](int buf, int c) {
        const int k0 = c * KC;
        const uint32_t sb = sbase + buf * STAGE_B;
        #pragma unroll
        for (int i = 0; i < 2; i++) {
            const int l   = tid + i * 256;
            const int row = l >> 2;
            const int ch  = (l & 3) * 16;
            const uint32_t soff = (uint32_t)(row * (LDT * 2)) + ch;
            const size_t ga = (size_t)(bm + row) * lda + k0;
            const size_t gb = (size_t)(bn + row) * ldb + k0;
            cpasync16(sb + 0 * MAT_B + soff, (const char*)(Ahi + ga) + ch);
            cpasync16(sb + 1 * MAT_B + soff, (const char*)(Alo + ga) + ch);
            cpasync16(sb + 2 * MAT_B + soff, (const char*)(Bhi + gb) + ch);
            cpasync16(sb + 3 * MAT_B + soff, (const char*)(Blo + gb) + ch);
        }
    };

    auto compute = [&](int buf) {
        const uint32_t base = sbase + buf * STAGE_B;
        #pragma unroll
        for (int ks = 0; ks < 2; ks++) {
            const uint32_t kb = (uint32_t)ks * 32;
            uint32_t bh[4][4], bl[4][4];
            #pragma unroll
            for (int u = 0; u < 4; u++) {
                ldsm4(bh[u][0], bh[u][1], bh[u][2], bh[u][3],
                      base + 2 * MAT_B + boff + u * (16 * LDT * 2) + kb);
                ldsm4(bl[u][0], bl[u][1], bl[u][2], bl[u][3],
                      base + 3 * MAT_B + boff + u * (16 * LDT * 2) + kb);
            }
            #pragma unroll
            for (int t = 0; t < 2; t++) {
                uint32_t ah[4], al[4];
                ldsm4(ah[0], ah[1], ah[2], ah[3],
                      base + 0 * MAT_B + aoff + t * (16 * LDT * 2) + kb);
                ldsm4(al[0], al[1], al[2], al[3],
                      base + 1 * MAT_B + aoff + t * (16 * LDT * 2) + kb);
                #pragma unroll
                for (int n = 0; n < 8; n++)
                    mma16816(acc[t][n], ah, &bh[n >> 1][(n & 1) * 2]);
                #pragma unroll
                for (int n = 0; n < 8; n++)
                    mma16816(acc[t][n], ah, &bl[n >> 1][(n & 1) * 2]);
                #pragma unroll
                for (int n = 0; n < 8; n++)
                    mma16816(acc[t][n], al, &bh[n >> 1][(n & 1) * 2]);
            }
        }
    };

    issue(0, 0);
    asm volatile("cp.async.commit_group;" ::: "memory");

    for (int c = 0; c < nk; ++c) {
        asm volatile("cp.async.wait_group 0;" ::: "memory");
        __syncthreads();
        if (c + 1 < nk) {
            issue((c + 1) & 1, c + 1);
            asm volatile("cp.async.commit_group;" ::: "memory");
        }
        compute(c & 1);
    }

    #pragma unroll
    for (int t = 0; t < 2; t++)
        #pragma unroll
        for (int n = 0; n < 8; n++) {
            const int row = bm + m_warp + t * 16 + (lane >> 2);
            const int col = bn + n_warp + n * 8 + (lane & 3) * 2;
            if (mode == 0) {
                float* C0 = Cf + (size_t)blockIdx.z * sC;
                *(float2*)(C0 + (size_t)row * ldc + col) =
                    make_float2(acc[t][n][0], acc[t][n][1]);
                *(float2*)(C0 + (size_t)(row + 8) * ldc + col) =
                    make_float2(acc[t][n][2], acc[t][n][3]);
            } else if (mode == 1) {
                bf162 h, l;
                split2(acc[t][n][0], acc[t][n][1], h, l);
                *(bf162*)(Chi + (size_t)row * ldc + col) = h;
                *(bf162*)(Clo + (size_t)row * ldc + col) = l;
                split2(acc[t][n][2], acc[t][n][3], h, l);
                *(bf162*)(Chi + (size_t)(row + 8) * ldc + col) = h;
                *(bf162*)(Clo + (size_t)(row + 8) * ldc + col) = l;
            } else {   // mode 4: fp16 hi/lo via reinterpreted pointers
                __half* Hh = (__half*)Chi;
                __half* Hl = (__half*)Clo;
                __half2 h, l;
                split2h(acc[t][n][0], acc[t][n][1], h, l);
                *(__half2*)(Hh + (size_t)row * ldc + col) = h;
                *(__half2*)(Hl + (size_t)row * ldc + col) = l;
                split2h(acc[t][n][2], acc[t][n][3], h, l);
                *(__half2*)(Hh + (size_t)(row + 8) * ldc + col) = h;
                *(__half2*)(Hl + (size_t)(row + 8) * ldc + col) = l;
            }
        }
}

// ---------------------------------------------------------------------------
// fp16 NT GEMM, 2-pass (A split fp16, B rounded fp16): C = sum_k A[m,k]*B[n,k]
// error ~2^-12 relative (B rounding only). 128x128, KC=32, 2 CTAs/SM.
// mode 0: fp32 C.  mode 3: fp16 rounded C.
// ---------------------------------------------------------------------------
#define H2_STAGE (3 * MAT_B)                // Ah, Al, Bh = 30720 B
#define H2_SMEM  (2 * H2_STAGE)             // 61440 B

__global__ __launch_bounds__(256, 2) void gemm_h2(
    const __half* __restrict__ Ah, const __half* __restrict__ Al,
    const __half* __restrict__ Bh,
    float* __restrict__ Cf, __half* __restrict__ C16,
    int lda, int ldb, int ldc, int K, int mode,
    size_t sA, size_t sB, size_t sC)
{
    extern __shared__ char smem[];
    Ah += (size_t)blockIdx.z * sA;  Al += (size_t)blockIdx.z * sA;
    Bh += (size_t)blockIdx.z * sB;

    const int tid  = threadIdx.x;
    const int lane = tid & 31;
    const int wid  = tid >> 5;
    const int bm   = blockIdx.y * 128;
    const int bn   = blockIdx.x * 128;
    const int m_warp = (wid & 3) * 32;
    const int n_warp = (wid >> 2) * 64;

    const uint32_t sbase = smem_u32(smem);
    const uint32_t aoff = (uint32_t)((m_warp + (lane & 15)) * (LDT * 2) + ((lane >> 4) * 8) * 2);
    const uint32_t boff = (uint32_t)((n_warp + (lane & 7) + ((lane & 16) ? 8 : 0)) * (LDT * 2)
                                     + ((lane & 8) ? 8 : 0) * 2);

    float acc[2][8][4];
    #pragma unroll
    for (int t = 0; t < 2; t++)
        #pragma unroll
        for (int n = 0; n < 8; n++)
            #pragma unroll
            for (int q = 0; q < 4; q++) acc[t][n][q] = 0.0f;

    const int nk = K / KC;

    auto issue = [&](int buf, int c) {
        const int k0 = c * KC;
        const uint32_t sb = sbase + buf * H2_STAGE;
        #pragma unroll
        for (int i = 0; i < 2; i++) {
            const int l   = tid + i * 256;
            const int row = l >> 2;
            const int ch  = (l & 3) * 16;
            const uint32_t soff = (uint32_t)(row * (LDT * 2)) + ch;
            const size_t ga = (size_t)(bm + row) * lda + k0;
            const size_t gb = (size_t)(bn + row) * ldb + k0;
            cpasync16(sb + 0 * MAT_B + soff, (const char*)(Ah + ga) + ch);
            cpasync16(sb + 1 * MAT_B + soff, (const char*)(Al + ga) + ch);
            cpasync16(sb + 2 * MAT_B + soff, (const char*)(Bh + gb) + ch);
        }
    };

    auto compute = [&](int buf) {
        const uint32_t base = sbase + buf * H2_STAGE;
        #pragma unroll
        for (int ks = 0; ks < 2; ks++) {
            const uint32_t kb = (uint32_t)ks * 32;
            uint32_t bh[4][4];
            #pragma unroll
            for (int u = 0; u < 4; u++)
                ldsm4(bh[u][0], bh[u][1], bh[u][2], bh[u][3],
                      base + 2 * MAT_B + boff + u * (16 * LDT * 2) + kb);
            #pragma unroll
            for (int t = 0; t < 2; t++) {
                uint32_t ah[4], al[4];
                ldsm4(ah[0], ah[1], ah[2], ah[3],
                      base + 0 * MAT_B + aoff + t * (16 * LDT * 2) + kb);
                ldsm4(al[0], al[1], al[2], al[3],
                      base + 1 * MAT_B + aoff + t * (16 * LDT * 2) + kb);
                #pragma unroll
                for (int n = 0; n < 8; n++)
                    mma16816h(acc[t][n], ah, &bh[n >> 1][(n & 1) * 2]);
                #pragma unroll
                for (int n = 0; n < 8; n++)
                    mma16816h(acc[t][n], al, &bh[n >> 1][(n & 1) * 2]);
            }
        }
    };

    issue(0, 0);
    asm volatile("cp.async.commit_group;" ::: "memory");

    for (int c = 0; c < nk; ++c) {
        asm volatile("cp.async.wait_group 0;" ::: "memory");
        __syncthreads();
        if (c + 1 < nk) {
            issue((c + 1) & 1, c + 1);
            asm volatile("cp.async.commit_group;" ::: "memory");
        }
        compute(c & 1);
    }

    #pragma unroll
    for (int t = 0; t < 2; t++)
        #pragma unroll
        for (int n = 0; n < 8; n++) {
            const int row = bm + m_warp + t * 16 + (lane >> 2);
            const int col = bn + n_warp + n * 8 + (lane & 3) * 2;
            if (mode == 0) {
                float* C0 = Cf + (size_t)blockIdx.z * sC;
                *(float2*)(C0 + (size_t)row * ldc + col) =
                    make_float2(acc[t][n][0], acc[t][n][1]);
                *(float2*)(C0 + (size_t)(row + 8) * ldc + col) =
                    make_float2(acc[t][n][2], acc[t][n][3]);
            } else {
                *(__half2*)(C16 + (size_t)row * ldc + col) =
                    __floats2half2_rn(acc[t][n][0], acc[t][n][1]);
                *(__half2*)(C16 + (size_t)(row + 8) * ldc + col) =
                    __floats2half2_rn(acc[t][n][2], acc[t][n][3]);
            }
        }
}

// ---------------------------------------------------------------------------
// Row softmax over 4096 fp32 scores -> fp16 hi/lo probabilities.
// ---------------------------------------------------------------------------
__global__ __launch_bounds__(256) void softmax_split_kernel(
    const float* __restrict__ Sm, __half* __restrict__ Ph, __half* __restrict__ Pl)
{
    const float* row = Sm + (size_t)blockIdx.x * SLEN;
    __half* ph = Ph + (size_t)blockIdx.x * SLEN;
    __half* pl = Pl + (size_t)blockIdx.x * SLEN;
    const int t    = threadIdx.x;
    const int lane = t & 31;
    const int warp = t >> 5;

    __shared__ float red[8];

    float v[16];
    float mx = -1e30f;
    #pragma unroll
    for (int i = 0; i < 16; i++) {
        v[i] = row[t + (i << 8)];
        mx = fmaxf(mx, v[i]);
    }
    #pragma unroll
    for (int o = 16; o > 0; o >>= 1)
        mx = fmaxf(mx, __shfl_xor_sync(0xffffffffu, mx, o));
    if (lane == 0) red[warp] = mx;
    __syncthreads();
    float rmax = red[0];
    #pragma unroll
    for (int i = 1; i < 8; i++) rmax = fmaxf(rmax, red[i]);

    float sum = 0.0f;
    #pragma unroll
    for (int i = 0; i < 16; i++) {
        v[i] = __expf(v[i] - rmax);
        sum += v[i];
    }
    #pragma unroll
    for (int o = 16; o > 0; o >>= 1)
        sum += __shfl_xor_sync(0xffffffffu, sum, o);
    __syncthreads();
    if (lane == 0) red[warp] = sum;
    __syncthreads();
    float rsum = 0.0f;
    #pragma unroll
    for (int i = 0; i < 8; i++) rsum += red[i];

    const float inv = 1.0f / rsum;
    #pragma unroll
    for (int i = 0; i < 16; i++) {
        float p = v[i] * inv;
        __half h = __float2half_rn(p);
        ph[t + (i << 8)] = h;
        pl[t + (i << 8)] = __float2half_rn(p - __half2float(h));
    }
}

// ---------------------------------------------------------------------------
// Final epilogue: y = attended + x;  out = y / ||y||_2 per 1024-row.
// ---------------------------------------------------------------------------
__global__ __launch_bounds__(256) void epilogue_kernel(
    const float* __restrict__ x, float* __restrict__ out)
{
    const size_t base = (size_t)blockIdx.x * DDIM;
    const int t    = threadIdx.x;
    const int lane = t & 31;
    const int warp = t >> 5;

    __shared__ float red[8];

    float4 a  = *(const float4*)(out + base + t * 4);
    float4 xv = *(const float4*)(x   + base + t * 4);
    float y0 = a.x + xv.x, y1 = a.y + xv.y, y2 = a.z + xv.z, y3 = a.w + xv.w;

    float ss = y0 * y0 + y1 * y1 + y2 * y2 + y3 * y3;
    #pragma unroll
    for (int o = 16; o > 0; o >>= 1)
        ss += __shfl_xor_sync(0xffffffffu, ss, o);
    if (lane == 0) red[warp] = ss;
    __syncthreads();
    float tot = 0.0f;
    #pragma unroll
    for (int i = 0; i < 8; i++) tot += red[i];

    const float inv = 1.0f / sqrtf(tot);
    *(float4*)(out + base + t * 4) =
        make_float4(y0 * inv, y1 * inv, y2 * inv, y3 * inv);
}

// ---------------------------------------------------------------------------
// Launch
// ---------------------------------------------------------------------------
extern "C" void kernel_launch(void* const* d_in, const int* in_sizes, int n_in,
                              void* d_out, int out_size)
{
    const float* x  = (const float*)d_in[0];
    const float* Wq = (const float*)d_in[1];
    const float* Wk = (const float*)d_in[2];
    const float* Wv = (const float*)d_in[3];
    float* out = (float*)d_out;

    bf16 *xhi, *xlo, *Wqthi, *Wqtlo, *Wkthi, *Wktlo, *Mthi, *Mtlo;
    __half *x16, *zh16, *zl16, *Wvh, *Wvl, *Vt16, *Ph, *Pl;
    float* Sc;
    cudaGetSymbolAddress((void**)&xhi,   g_xhi);    cudaGetSymbolAddress((void**)&xlo,   g_xlo);
    cudaGetSymbolAddress((void**)&Wqthi, g_Wqthi);  cudaGetSymbolAddress((void**)&Wqtlo, g_Wqtlo);
    cudaGetSymbolAddress((void**)&Wkthi, g_Wkthi);  cudaGetSymbolAddress((void**)&Wktlo, g_Wktlo);
    cudaGetSymbolAddress((void**)&Mthi,  g_Mthi);   cudaGetSymbolAddress((void**)&Mtlo,  g_Mtlo);
    cudaGetSymbolAddress((void**)&x16,   g_x16);
    cudaGetSymbolAddress((void**)&zh16,  g_zh16);   cudaGetSymbolAddress((void**)&zl16,  g_zl16);
    cudaGetSymbolAddress((void**)&Wvh,   g_Wvh);    cudaGetSymbolAddress((void**)&Wvl,   g_Wvl);
    cudaGetSymbolAddress((void**)&Vt16,  g_Vt16);
    cudaGetSymbolAddress((void**)&Ph,    g_Ph);     cudaGetSymbolAddress((void**)&Pl,    g_Pl);
    cudaGetSymbolAddress((void**)&Sc,    g_S);

    cudaFuncSetAttribute(gemm_bf, cudaFuncAttributeMaxDynamicSharedMemorySize, SMEM_DYN);
    cudaFuncSetAttribute(gemm_h2, cudaFuncAttributeMaxDynamicSharedMemorySize, H2_SMEM);

    const size_t sQKV = (size_t)SLEN * DDIM;
    const size_t sSS  = (size_t)SLEN * SLEN;
    dim3 blk(256);

    // 0) conversions
    conv_split<<<(MTOT * DDIM) / 1024, blk>>>(x, xhi, xlo);
    conv_round16<<<(MTOT * DDIM) / 1024, blk>>>(x, x16);
    conv_split16<<<(DDIM * DDIM) / 1024, blk>>>(Wv, Wvh, Wvl);
    dim3 gtr(DDIM / 32, DDIM / 32, 1);
    trans_split<<<gtr, blk>>>(Wq, Wqthi, Wqtlo);
    trans_split<<<gtr, blk>>>(Wk, Wkthi, Wktlo);

    // 1) Mt = Wkt · Wqtᵀ  (bf16 3-pass, bf16 hi/lo out)
    dim3 gM(DDIM / 128, DDIM / 128, 1);
    gemm_bf<<<gM, blk, SMEM_DYN>>>(Wkthi, Wktlo, Wqthi, Wqtlo, nullptr, Mthi, Mtlo,
                                   DDIM, DDIM, DDIM, DDIM, 1, 0, 0, 0);

    // 2) z = x · Mtᵀ  (bf16 3-pass, fp16 hi/lo out for the scores GEMM)
    dim3 gz(DDIM / 128, MTOT / 128, 1);
    gemm_bf<<<gz, blk, SMEM_DYN>>>(xhi, xlo, Mthi, Mtlo, nullptr,
                                   (bf16*)zh16, (bf16*)zl16,
                                   DDIM, DDIM, DDIM, DDIM, 4, 0, 0, 0);

    // 3) Vt = Wv · xᵀ  (fp16 2-pass, fp16 out, coalesced)
    dim3 gv(MTOT / 128, DDIM / 128, 1);
    gemm_h2<<<gv, blk, H2_SMEM>>>(Wvh, Wvl, x16, nullptr, Vt16,
                                  DDIM, DDIM, MTOT, DDIM, 3, 0, 0, 0);

    // 4) scores = z · x16ᵀ per batch (fp16 2-pass, fp32 out)
    dim3 gsc(SLEN / 128, SLEN / 128, BATCH);
    gemm_h2<<<gsc, blk, H2_SMEM>>>(zh16, zl16, x16, Sc, nullptr,
                                   DDIM, DDIM, SLEN, DDIM, 0, sQKV, sQKV, sSS);

    // 5) softmax -> P fp16 hi/lo (BETA = 1)
    softmax_split_kernel<<<MTOT, blk>>>(Sc, Ph, Pl);

    // 6) attended = P · Vtᵀ per batch (fp16 2-pass, fp32 out into d_out)
    dim3 gav(DDIM / 128, SLEN / 128, BATCH);
    gemm_h2<<<gav, blk, H2_SMEM>>>(Ph, Pl, Vt16, out, nullptr,
                                   SLEN, MTOT, DDIM, SLEN, 0,
                                   sSS, (size_t)SLEN, sQKV);

    // 7) y = attended + x; L2 normalize
    epilogue_kernel<<<MTOT, blk>>>(x, out);
}

// round 13
// speedup vs baseline: 1.8349x; 1.1606x over previous
#include <cuda_runtime.h>
#include <cuda_bf16.h>
#include <cuda_fp16.h>
#include <cstdint>
#include <cstddef>

#define BATCH   4
#define SLEN    4096
#define DDIM    1024
#define MTOT    (BATCH * SLEN)          // 16384

typedef __nv_bfloat16  bf16;
typedef __nv_bfloat162 bf162;

// ---------------------------------------------------------------------------
// Scratch (allocation-free rule: __device__ globals).
// z path (bf16 3-pass):   z = x·M, M = Wqᵀ·Wk           (K projection gone)
// scores (fp16 2-pass):   scores = (zh+zl)·x16ᵀ          (err: x rounding)
// PV path (fp16 1-pass):  Vᵀ = Wv·xᵀ (2-pass), attended = P16·Vᵀᵀ (1-pass)
// ---------------------------------------------------------------------------
__device__ bf16 g_xhi [(size_t)MTOT * DDIM];
__device__ bf16 g_xlo [(size_t)MTOT * DDIM];
__device__ bf16 g_Wqthi[(size_t)DDIM * DDIM];
__device__ bf16 g_Wqtlo[(size_t)DDIM * DDIM];
__device__ bf16 g_Wkthi[(size_t)DDIM * DDIM];
__device__ bf16 g_Wktlo[(size_t)DDIM * DDIM];
__device__ bf16 g_Mthi[(size_t)DDIM * DDIM];
__device__ bf16 g_Mtlo[(size_t)DDIM * DDIM];
__device__ float g_S  [(size_t)MTOT * SLEN];
// fp16 operands
__device__ __half g_x16 [(size_t)MTOT * DDIM];   // x rounded to fp16
__device__ __half g_zh16[(size_t)MTOT * DDIM];   // z split fp16
__device__ __half g_zl16[(size_t)MTOT * DDIM];
__device__ __half g_Wvh [(size_t)DDIM * DDIM];   // Wv split fp16
__device__ __half g_Wvl [(size_t)DDIM * DDIM];
__device__ __half g_Vt16[(size_t)DDIM * MTOT];   // Vᵀ fp16 [D, MTOT]
__device__ __half g_Ph  [(size_t)MTOT * SLEN];   // P rounded fp16

// ---------------------------------------------------------------------------
// Helpers (arch-agnostic PTX only: plain sm_103 target)
// ---------------------------------------------------------------------------
__device__ __forceinline__ uint32_t smem_u32(const void* p) {
    uint32_t a;
    asm("{ .reg .u64 t; cvta.to.shared.u64 t, %1; cvt.u32.u64 %0, t; }" : "=r"(a) : "l"(p));
    return a;
}
__device__ __forceinline__ void ldsm4(uint32_t& r0, uint32_t& r1, uint32_t& r2, uint32_t& r3,
                                      uint32_t addr) {
    asm volatile("ldmatrix.sync.aligned.m8n8.x4.shared.b16 {%0,%1,%2,%3}, [%4];"
                 : "=r"(r0), "=r"(r1), "=r"(r2), "=r"(r3) : "r"(addr));
}
__device__ __forceinline__ void mma16816(float* c, const uint32_t* a, const uint32_t* b) {
    asm volatile(
        "mma.sync.aligned.m16n8k16.row.col.f32.bf16.bf16.f32 "
        "{%0,%1,%2,%3}, {%4,%5,%6,%7}, {%8,%9}, {%0,%1,%2,%3};"
        : "+f"(c[0]), "+f"(c[1]), "+f"(c[2]), "+f"(c[3])
        : "r"(a[0]), "r"(a[1]), "r"(a[2]), "r"(a[3]), "r"(b[0]), "r"(b[1]));
}
__device__ __forceinline__ void mma16816h(float* c, const uint32_t* a, const uint32_t* b) {
    asm volatile(
        "mma.sync.aligned.m16n8k16.row.col.f32.f16.f16.f32 "
        "{%0,%1,%2,%3}, {%4,%5,%6,%7}, {%8,%9}, {%0,%1,%2,%3};"
        : "+f"(c[0]), "+f"(c[1]), "+f"(c[2]), "+f"(c[3])
        : "r"(a[0]), "r"(a[1]), "r"(a[2]), "r"(a[3]), "r"(b[0]), "r"(b[1]));
}
__device__ __forceinline__ void cpasync16(uint32_t dst, const void* src) {
    asm volatile("cp.async.cg.shared.global [%0], [%1], 16;" :: "r"(dst), "l"(src));
}
__device__ __forceinline__ void split2(float x, float y, bf162& h, bf162& l) {
    h = __floats2bfloat162_rn(x, y);
    float2 f = __bfloat1622float2(h);
    l = __floats2bfloat162_rn(x - f.x, y - f.y);
}
__device__ __forceinline__ void split2h(float x, float y, __half2& h, __half2& l) {
    h = __floats2half2_rn(x, y);
    float2 f = __half22float2(h);
    l = __floats2half2_rn(x - f.x, y - f.y);
}

// ---------------------------------------------------------------------------
// Conversion kernels
// ---------------------------------------------------------------------------
__global__ __launch_bounds__(256) void conv_split(
    const float* __restrict__ src, bf16* __restrict__ hi, bf16* __restrict__ lo)
{
    size_t i = ((size_t)blockIdx.x * 256 + threadIdx.x) * 4;
    float4 v = *(const float4*)(src + i);
    bf162 h0, l0, h1, l1;
    split2(v.x, v.y, h0, l0);
    split2(v.z, v.w, h1, l1);
    *(bf162*)(hi + i)     = h0;
    *(bf162*)(hi + i + 2) = h1;
    *(bf162*)(lo + i)     = l0;
    *(bf162*)(lo + i + 2) = l1;
}

__global__ __launch_bounds__(256) void conv_round16(
    const float* __restrict__ src, __half* __restrict__ dst)
{
    size_t i = ((size_t)blockIdx.x * 256 + threadIdx.x) * 4;
    float4 v = *(const float4*)(src + i);
    *(__half2*)(dst + i)     = __floats2half2_rn(v.x, v.y);
    *(__half2*)(dst + i + 2) = __floats2half2_rn(v.z, v.w);
}

__global__ __launch_bounds__(256) void conv_split16(
    const float* __restrict__ src, __half* __restrict__ hi, __half* __restrict__ lo)
{
    size_t i = ((size_t)blockIdx.x * 256 + threadIdx.x) * 4;
    float4 v = *(const float4*)(src + i);
    __half2 h0, l0, h1, l1;
    split2h(v.x, v.y, h0, l0);
    split2h(v.z, v.w, h1, l1);
    *(__half2*)(hi + i)     = h0;
    *(__half2*)(hi + i + 2) = h1;
    *(__half2*)(lo + i)     = l0;
    *(__half2*)(lo + i + 2) = l1;
}

// Transpose + split: out[i,e] = src[e,i] for 1024x1024 fp32, bf16 hi/lo out.
__global__ __launch_bounds__(256) void trans_split(
    const float* __restrict__ src, bf16* __restrict__ hi, bf16* __restrict__ lo)
{
    __shared__ float t[32][33];
    const int tx = threadIdx.x & 31;
    const int ty = threadIdx.x >> 5;
    const int bx = blockIdx.x * 32;
    const int by = blockIdx.y * 32;
    #pragma unroll
    for (int i = 0; i < 4; i++)
        t[ty + i * 8][tx] = src[(size_t)(by + ty + i * 8) * DDIM + bx + tx];
    __syncthreads();
    #pragma unroll
    for (int i = 0; i < 4; i++) {
        const int r = ty + i * 8;
        float v = t[tx][r];
        bf16 h = __float2bfloat16_rn(v);
        bf16 l = __float2bfloat16_rn(v - __bfloat162float(h));
        hi[(size_t)(bx + r) * DDIM + by + tx] = h;
        lo[(size_t)(bx + r) * DDIM + by + tx] = l;
    }
}

// ---------------------------------------------------------------------------
// bf16 NT GEMM, 3-pass fp32 emulation. 128x128, KC=32, 2-stage cp.async,
// 2 CTAs/SM. mode 0: fp32 C. mode 1: bf16 hi/lo out. mode 4: fp16 hi/lo out.
// ---------------------------------------------------------------------------
#define KC       32
#define LDT      40
#define MAT_B    (128 * LDT * 2)            // 10240 B
#define STAGE_B  (4 * MAT_B)                // 40960 B
#define SMEM_DYN (2 * STAGE_B)              // 81920 B

__global__ __launch_bounds__(256, 2) void gemm_bf(
    const bf16* __restrict__ Ahi, const bf16* __restrict__ Alo,
    const bf16* __restrict__ Bhi, const bf16* __restrict__ Blo,
    float* __restrict__ Cf, bf16* __restrict__ Chi, bf16* __restrict__ Clo,
    int lda, int ldb, int ldc, int K, int mode,
    size_t sA, size_t sB, size_t sC)
{
    extern __shared__ char smem[];
    Ahi += (size_t)blockIdx.z * sA;  Alo += (size_t)blockIdx.z * sA;
    Bhi += (size_t)blockIdx.z * sB;  Blo += (size_t)blockIdx.z * sB;

    const int tid  = threadIdx.x;
    const int lane = tid & 31;
    const int wid  = tid >> 5;
    const int bm   = blockIdx.y * 128;
    const int bn   = blockIdx.x * 128;
    const int m_warp = (wid & 3) * 32;
    const int n_warp = (wid >> 2) * 64;

    const uint32_t sbase = smem_u32(smem);
    const uint32_t aoff = (uint32_t)((m_warp + (lane & 15)) * (LDT * 2) + ((lane >> 4) * 8) * 2);
    const uint32_t boff = (uint32_t)((n_warp + (lane & 7) + ((lane & 16) ? 8 : 0)) * (LDT * 2)
                                     + ((lane & 8) ? 8 : 0) * 2);

    float acc[2][8][4];
    #pragma unroll
    for (int t = 0; t < 2; t++)
        #pragma unroll
        for (int n = 0; n < 8; n++)
            #pragma unroll
            for (int q = 0; q < 4; q++) acc[t][n][q] = 0.0f;

    const int nk = K / KC;

    auto issue = [&](int buf, int c) {
        const int k0 = c * KC;
        const uint32_t sb = sbase + buf * STAGE_B;
        #pragma unroll
        for (int i = 0; i < 2; i++) {
            const int l   = tid + i * 256;
            const int row = l >> 2;
            const int ch  = (l & 3) * 16;
            const uint32_t soff = (uint32_t)(row * (LDT * 2)) + ch;
            const size_t ga = (size_t)(bm + row) * lda + k0;
            const size_t gb = (size_t)(bn + row) * ldb + k0;
            cpasync16(sb + 0 * MAT_B + soff, (const char*)(Ahi + ga) + ch);
            cpasync16(sb + 1 * MAT_B + soff, (const char*)(Alo + ga) + ch);
            cpasync16(sb + 2 * MAT_B + soff, (const char*)(Bhi + gb) + ch);
            cpasync16(sb + 3 * MAT_B + soff, (const char*)(Blo + gb) + ch);
        }
    };

    auto compute = [&](int buf) {
        const uint32_t base = sbase + buf * STAGE_B;
        #pragma unroll
        for (int ks = 0; ks < 2; ks++) {
            const uint32_t kb = (uint32_t)ks * 32;
            uint32_t bh[4][4], bl[4][4];
            #pragma unroll
            for (int u = 0; u < 4; u++) {
                ldsm4(bh[u][0], bh[u][1], bh[u][2], bh[u][3],
                      base + 2 * MAT_B + boff + u * (16 * LDT * 2) + kb);
                ldsm4(bl[u][0], bl[u][1], bl[u][2], bl[u][3],
                      base + 3 * MAT_B + boff + u * (16 * LDT * 2) + kb);
            }
            #pragma unroll
            for (int t = 0; t < 2; t++) {
                uint32_t ah[4], al[4];
                ldsm4(ah[0], ah[1], ah[2], ah[3],
                      base + 0 * MAT_B + aoff + t * (16 * LDT * 2) + kb);
                ldsm4(al[0], al[1], al[2], al[3],
                      base + 1 * MAT_B + aoff + t * (16 * LDT * 2) + kb);
                #pragma unroll
                for (int n = 0; n < 8; n++)
                    mma16816(acc[t][n], ah, &bh[n >> 1][(n & 1) * 2]);
                #pragma unroll
                for (int n = 0; n < 8; n++)
                    mma16816(acc[t][n], ah, &bl[n >> 1][(n & 1) * 2]);
                #pragma unroll
                for (int n = 0; n < 8; n++)
                    mma16816(acc[t][n], al, &bh[n >> 1][(n & 1) * 2]);
            }
        }
    };

    issue(0, 0);
    asm volatile("cp.async.commit_group;" ::: "memory");

    for (int c = 0; c < nk; ++c) {
        asm volatile("cp.async.wait_group 0;" ::: "memory");
        __syncthreads();
        if (c + 1 < nk) {
            issue((c + 1) & 1, c + 1);
            asm volatile("cp.async.commit_group;" ::: "memory");
        }
        compute(c & 1);
    }

    #pragma unroll
    for (int t = 0; t < 2; t++)
        #pragma unroll
        for (int n = 0; n < 8; n++) {
            const int row = bm + m_warp + t * 16 + (lane >> 2);
            const int col = bn + n_warp + n * 8 + (lane & 3) * 2;
            if (mode == 0) {
                float* C0 = Cf + (size_t)blockIdx.z * sC;
                *(float2*)(C0 + (size_t)row * ldc + col) =
                    make_float2(acc[t][n][0], acc[t][n][1]);
                *(float2*)(C0 + (size_t)(row + 8) * ldc + col) =
                    make_float2(acc[t][n][2], acc[t][n][3]);
            } else if (mode == 1) {
                bf162 h, l;
                split2(acc[t][n][0], acc[t][n][1], h, l);
                *(bf162*)(Chi + (size_t)row * ldc + col) = h;
                *(bf162*)(Clo + (size_t)row * ldc + col) = l;
                split2(acc[t][n][2], acc[t][n][3], h, l);
                *(bf162*)(Chi + (size_t)(row + 8) * ldc + col) = h;
                *(bf162*)(Clo + (size_t)(row + 8) * ldc + col) = l;
            } else {   // mode 4: fp16 hi/lo via reinterpreted pointers
                __half* Hh = (__half*)Chi;
                __half* Hl = (__half*)Clo;
                __half2 h, l;
                split2h(acc[t][n][0], acc[t][n][1], h, l);
                *(__half2*)(Hh + (size_t)row * ldc + col) = h;
                *(__half2*)(Hl + (size_t)row * ldc + col) = l;
                split2h(acc[t][n][2], acc[t][n][3], h, l);
                *(__half2*)(Hh + (size_t)(row + 8) * ldc + col) = h;
                *(__half2*)(Hl + (size_t)(row + 8) * ldc + col) = l;
            }
        }
}

// ---------------------------------------------------------------------------
// fp16 NT GEMM, 2-pass (A split fp16, B rounded fp16).
// mode 0: fp32 C.  mode 3: fp16 rounded C.
// ---------------------------------------------------------------------------
#define H2_STAGE (3 * MAT_B)                // Ah, Al, Bh = 30720 B
#define H2_SMEM  (2 * H2_STAGE)             // 61440 B

__global__ __launch_bounds__(256, 2) void gemm_h2(
    const __half* __restrict__ Ah, const __half* __restrict__ Al,
    const __half* __restrict__ Bh,
    float* __restrict__ Cf, __half* __restrict__ C16,
    int lda, int ldb, int ldc, int K, int mode,
    size_t sA, size_t sB, size_t sC)
{
    extern __shared__ char smem[];
    Ah += (size_t)blockIdx.z * sA;  Al += (size_t)blockIdx.z * sA;
    Bh += (size_t)blockIdx.z * sB;

    const int tid  = threadIdx.x;
    const int lane = tid & 31;
    const int wid  = tid >> 5;
    const int bm   = blockIdx.y * 128;
    const int bn   = blockIdx.x * 128;
    const int m_warp = (wid & 3) * 32;
    const int n_warp = (wid >> 2) * 64;

    const uint32_t sbase = smem_u32(smem);
    const uint32_t aoff = (uint32_t)((m_warp + (lane & 15)) * (LDT * 2) + ((lane >> 4) * 8) * 2);
    const uint32_t boff = (uint32_t)((n_warp + (lane & 7) + ((lane & 16) ? 8 : 0)) * (LDT * 2)
                                     + ((lane & 8) ? 8 : 0) * 2);

    float acc[2][8][4];
    #pragma unroll
    for (int t = 0; t < 2; t++)
        #pragma unroll
        for (int n = 0; n < 8; n++)
            #pragma unroll
            for (int q = 0; q < 4; q++) acc[t][n][q] = 0.0f;

    const int nk = K / KC;

    auto issue = [&](int buf, int c) {
        const int k0 = c * KC;
        const uint32_t sb = sbase + buf * H2_STAGE;
        #pragma unroll
        for (int i = 0; i < 2; i++) {
            const int l   = tid + i * 256;
            const int row = l >> 2;
            const int ch  = (l & 3) * 16;
            const uint32_t soff = (uint32_t)(row * (LDT * 2)) + ch;
            const size_t ga = (size_t)(bm + row) * lda + k0;
            const size_t gb = (size_t)(bn + row) * ldb + k0;
            cpasync16(sb + 0 * MAT_B + soff, (const char*)(Ah + ga) + ch);
            cpasync16(sb + 1 * MAT_B + soff, (const char*)(Al + ga) + ch);
            cpasync16(sb + 2 * MAT_B + soff, (const char*)(Bh + gb) + ch);
        }
    };

    auto compute = [&](int buf) {
        const uint32_t base = sbase + buf * H2_STAGE;
        #pragma unroll
        for (int ks = 0; ks < 2; ks++) {
            const uint32_t kb = (uint32_t)ks * 32;
            uint32_t bh[4][4];
            #pragma unroll
            for (int u = 0; u < 4; u++)
                ldsm4(bh[u][0], bh[u][1], bh[u][2], bh[u][3],
                      base + 2 * MAT_B + boff + u * (16 * LDT * 2) + kb);
            #pragma unroll
            for (int t = 0; t < 2; t++) {
                uint32_t ah[4], al[4];
                ldsm4(ah[0], ah[1], ah[2], ah[3],
                      base + 0 * MAT_B + aoff + t * (16 * LDT * 2) + kb);
                ldsm4(al[0], al[1], al[2], al[3],
                      base + 1 * MAT_B + aoff + t * (16 * LDT * 2) + kb);
                #pragma unroll
                for (int n = 0; n < 8; n++)
                    mma16816h(acc[t][n], ah, &bh[n >> 1][(n & 1) * 2]);
                #pragma unroll
                for (int n = 0; n < 8; n++)
                    mma16816h(acc[t][n], al, &bh[n >> 1][(n & 1) * 2]);
            }
        }
    };

    issue(0, 0);
    asm volatile("cp.async.commit_group;" ::: "memory");

    for (int c = 0; c < nk; ++c) {
        asm volatile("cp.async.wait_group 0;" ::: "memory");
        __syncthreads();
        if (c + 1 < nk) {
            issue((c + 1) & 1, c + 1);
            asm volatile("cp.async.commit_group;" ::: "memory");
        }
        compute(c & 1);
    }

    #pragma unroll
    for (int t = 0; t < 2; t++)
        #pragma unroll
        for (int n = 0; n < 8; n++) {
            const int row = bm + m_warp + t * 16 + (lane >> 2);
            const int col = bn + n_warp + n * 8 + (lane & 3) * 2;
            if (mode == 0) {
                float* C0 = Cf + (size_t)blockIdx.z * sC;
                *(float2*)(C0 + (size_t)row * ldc + col) =
                    make_float2(acc[t][n][0], acc[t][n][1]);
                *(float2*)(C0 + (size_t)(row + 8) * ldc + col) =
                    make_float2(acc[t][n][2], acc[t][n][3]);
            } else {
                *(__half2*)(C16 + (size_t)row * ldc + col) =
                    __floats2half2_rn(acc[t][n][0], acc[t][n][1]);
                *(__half2*)(C16 + (size_t)(row + 8) * ldc + col) =
                    __floats2half2_rn(acc[t][n][2], acc[t][n][3]);
            }
        }
}

// ---------------------------------------------------------------------------
// fp16 NT GEMM, 1-pass (A rounded fp16, B rounded fp16): fp32 out.
// Used for attended = P16 · Vt16ᵀ.
// ---------------------------------------------------------------------------
#define H1_STAGE (2 * MAT_B)                // Ah, Bh = 20480 B
#define H1_SMEM  (2 * H1_STAGE)             // 40960 B

__global__ __launch_bounds__(256, 2) void gemm_h1(
    const __half* __restrict__ Ah, const __half* __restrict__ Bh,
    float* __restrict__ Cf,
    int lda, int ldb, int ldc, int K,
    size_t sA, size_t sB, size_t sC)
{
    extern __shared__ char smem[];
    Ah += (size_t)blockIdx.z * sA;
    Bh += (size_t)blockIdx.z * sB;

    const int tid  = threadIdx.x;
    const int lane = tid & 31;
    const int wid  = tid >> 5;
    const int bm   = blockIdx.y * 128;
    const int bn   = blockIdx.x * 128;
    const int m_warp = (wid & 3) * 32;
    const int n_warp = (wid >> 2) * 64;

    const uint32_t sbase = smem_u32(smem);
    const uint32_t aoff = (uint32_t)((m_warp + (lane & 15)) * (LDT * 2) + ((lane >> 4) * 8) * 2);
    const uint32_t boff = (uint32_t)((n_warp + (lane & 7) + ((lane & 16) ? 8 : 0)) * (LDT * 2)
                                     + ((lane & 8) ? 8 : 0) * 2);

    float acc[2][8][4];
    #pragma unroll
    for (int t = 0; t < 2; t++)
        #pragma unroll
        for (int n = 0; n < 8; n++)
            #pragma unroll
            for (int q = 0; q < 4; q++) acc[t][n][q] = 0.0f;

    const int nk = K / KC;

    auto issue = [&](int buf, int c) {
        const int k0 = c * KC;
        const uint32_t sb = sbase + buf * H1_STAGE;
        #pragma unroll
        for (int i = 0; i < 2; i++) {
            const int l   = tid + i * 256;
            const int row = l >> 2;
            const int ch  = (l & 3) * 16;
            const uint32_t soff = (uint32_t)(row * (LDT * 2)) + ch;
            const size_t ga = (size_t)(bm + row) * lda + k0;
            const size_t gb = (size_t)(bn + row) * ldb + k0;
            cpasync16(sb + 0 * MAT_B + soff, (const char*)(Ah + ga) + ch);
            cpasync16(sb + 1 * MAT_B + soff, (const char*)(Bh + gb) + ch);
        }
    };

    auto compute = [&](int buf) {
        const uint32_t base = sbase + buf * H1_STAGE;
        #pragma unroll
        for (int ks = 0; ks < 2; ks++) {
            const uint32_t kb = (uint32_t)ks * 32;
            uint32_t bh[4][4];
            #pragma unroll
            for (int u = 0; u < 4; u++)
                ldsm4(bh[u][0], bh[u][1], bh[u][2], bh[u][3],
                      base + 1 * MAT_B + boff + u * (16 * LDT * 2) + kb);
            #pragma unroll
            for (int t = 0; t < 2; t++) {
                uint32_t ah[4];
                ldsm4(ah[0], ah[1], ah[2], ah[3],
                      base + 0 * MAT_B + aoff + t * (16 * LDT * 2) + kb);
                #pragma unroll
                for (int n = 0; n < 8; n++)
                    mma16816h(acc[t][n], ah, &bh[n >> 1][(n & 1) * 2]);
            }
        }
    };

    issue(0, 0);
    asm volatile("cp.async.commit_group;" ::: "memory");

    for (int c = 0; c < nk; ++c) {
        asm volatile("cp.async.wait_group 0;" ::: "memory");
        __syncthreads();
        if (c + 1 < nk) {
            issue((c + 1) & 1, c + 1);
            asm volatile("cp.async.commit_group;" ::: "memory");
        }
        compute(c & 1);
    }

    #pragma unroll
    for (int t = 0; t < 2; t++)
        #pragma unroll
        for (int n = 0; n < 8; n++) {
            const int row = bm + m_warp + t * 16 + (lane >> 2);
            const int col = bn + n_warp + n * 8 + (lane & 3) * 2;
            float* C0 = Cf + (size_t)blockIdx.z * sC;
            *(float2*)(C0 + (size_t)row * ldc + col) =
                make_float2(acc[t][n][0], acc[t][n][1]);
            *(float2*)(C0 + (size_t)(row + 8) * ldc + col) =
                make_float2(acc[t][n][2], acc[t][n][3]);
        }
}

// ---------------------------------------------------------------------------
// Row softmax over 4096 fp32 scores -> fp16 rounded probabilities.
// ---------------------------------------------------------------------------
__global__ __launch_bounds__(256) void softmax_kernel16(
    const float* __restrict__ Sm, __half* __restrict__ Ph)
{
    const float* row = Sm + (size_t)blockIdx.x * SLEN;
    __half* ph = Ph + (size_t)blockIdx.x * SLEN;
    const int t    = threadIdx.x;
    const int lane = t & 31;
    const int warp = t >> 5;

    __shared__ float red[8];

    float v[16];
    float mx = -1e30f;
    #pragma unroll
    for (int i = 0; i < 16; i++) {
        v[i] = row[t + (i << 8)];
        mx = fmaxf(mx, v[i]);
    }
    #pragma unroll
    for (int o = 16; o > 0; o >>= 1)
        mx = fmaxf(mx, __shfl_xor_sync(0xffffffffu, mx, o));
    if (lane == 0) red[warp] = mx;
    __syncthreads();
    float rmax = red[0];
    #pragma unroll
    for (int i = 1; i < 8; i++) rmax = fmaxf(rmax, red[i]);

    float sum = 0.0f;
    #pragma unroll
    for (int i = 0; i < 16; i++) {
        v[i] = __expf(v[i] - rmax);
        sum += v[i];
    }
    #pragma unroll
    for (int o = 16; o > 0; o >>= 1)
        sum += __shfl_xor_sync(0xffffffffu, sum, o);
    __syncthreads();
    if (lane == 0) red[warp] = sum;
    __syncthreads();
    float rsum = 0.0f;
    #pragma unroll
    for (int i = 0; i < 8; i++) rsum += red[i];

    const float inv = 1.0f / rsum;
    #pragma unroll
    for (int i = 0; i < 16; i++)
        ph[t + (i << 8)] = __float2half_rn(v[i] * inv);
}

// ---------------------------------------------------------------------------
// Final epilogue: y = attended + x;  out = y / ||y||_2 per 1024-row.
// ---------------------------------------------------------------------------
__global__ __launch_bounds__(256) void epilogue_kernel(
    const float* __restrict__ x, float* __restrict__ out)
{
    const size_t base = (size_t)blockIdx.x * DDIM;
    const int t    = threadIdx.x;
    const int lane = t & 31;
    const int warp = t >> 5;

    __shared__ float red[8];

    float4 a  = *(const float4*)(out + base + t * 4);
    float4 xv = *(const float4*)(x   + base + t * 4);
    float y0 = a.x + xv.x, y1 = a.y + xv.y, y2 = a.z + xv.z, y3 = a.w + xv.w;

    float ss = y0 * y0 + y1 * y1 + y2 * y2 + y3 * y3;
    #pragma unroll
    for (int o = 16; o > 0; o >>= 1)
        ss += __shfl_xor_sync(0xffffffffu, ss, o);
    if (lane == 0) red[warp] = ss;
    __syncthreads();
    float tot = 0.0f;
    #pragma unroll
    for (int i = 0; i < 8; i++) tot += red[i];

    const float inv = 1.0f / sqrtf(tot);
    *(float4*)(out + base + t * 4) =
        make_float4(y0 * inv, y1 * inv, y2 * inv, y3 * inv);
}

// ---------------------------------------------------------------------------
// Launch
// ---------------------------------------------------------------------------
extern "C" void kernel_launch(void* const* d_in, const int* in_sizes, int n_in,
                              void* d_out, int out_size)
{
    const float* x  = (const float*)d_in[0];
    const float* Wq = (const float*)d_in[1];
    const float* Wk = (const float*)d_in[2];
    const float* Wv = (const float*)d_in[3];
    float* out = (float*)d_out;

    bf16 *xhi, *xlo, *Wqthi, *Wqtlo, *Wkthi, *Wktlo, *Mthi, *Mtlo;
    __half *x16, *zh16, *zl16, *Wvh, *Wvl, *Vt16, *Ph;
    float* Sc;
    cudaGetSymbolAddress((void**)&xhi,   g_xhi);    cudaGetSymbolAddress((void**)&xlo,   g_xlo);
    cudaGetSymbolAddress((void**)&Wqthi, g_Wqthi);  cudaGetSymbolAddress((void**)&Wqtlo, g_Wqtlo);
    cudaGetSymbolAddress((void**)&Wkthi, g_Wkthi);  cudaGetSymbolAddress((void**)&Wktlo, g_Wktlo);
    cudaGetSymbolAddress((void**)&Mthi,  g_Mthi);   cudaGetSymbolAddress((void**)&Mtlo,  g_Mtlo);
    cudaGetSymbolAddress((void**)&x16,   g_x16);
    cudaGetSymbolAddress((void**)&zh16,  g_zh16);   cudaGetSymbolAddress((void**)&zl16,  g_zl16);
    cudaGetSymbolAddress((void**)&Wvh,   g_Wvh);    cudaGetSymbolAddress((void**)&Wvl,   g_Wvl);
    cudaGetSymbolAddress((void**)&Vt16,  g_Vt16);
    cudaGetSymbolAddress((void**)&Ph,    g_Ph);
    cudaGetSymbolAddress((void**)&Sc,    g_S);

    cudaFuncSetAttribute(gemm_bf, cudaFuncAttributeMaxDynamicSharedMemorySize, SMEM_DYN);
    cudaFuncSetAttribute(gemm_h2, cudaFuncAttributeMaxDynamicSharedMemorySize, H2_SMEM);
    cudaFuncSetAttribute(gemm_h1, cudaFuncAttributeMaxDynamicSharedMemorySize, H1_SMEM);

    const size_t sQKV = (size_t)SLEN * DDIM;
    const size_t sSS  = (size_t)SLEN * SLEN;
    dim3 blk(256);

    // 0) conversions
    conv_split<<<(MTOT * DDIM) / 1024, blk>>>(x, xhi, xlo);
    conv_round16<<<(MTOT * DDIM) / 1024, blk>>>(x, x16);
    conv_split16<<<(DDIM * DDIM) / 1024, blk>>>(Wv, Wvh, Wvl);
    dim3 gtr(DDIM / 32, DDIM / 32, 1);
    trans_split<<<gtr, blk>>>(Wq, Wqthi, Wqtlo);
    trans_split<<<gtr, blk>>>(Wk, Wkthi, Wktlo);

    // 1) Mt = Wkt · Wqtᵀ  (bf16 3-pass, bf16 hi/lo out)
    dim3 gM(DDIM / 128, DDIM / 128, 1);
    gemm_bf<<<gM, blk, SMEM_DYN>>>(Wkthi, Wktlo, Wqthi, Wqtlo, nullptr, Mthi, Mtlo,
                                   DDIM, DDIM, DDIM, DDIM, 1, 0, 0, 0);

    // 2) z = x · Mtᵀ  (bf16 3-pass, fp16 hi/lo out for the scores GEMM)
    dim3 gz(DDIM / 128, MTOT / 128, 1);
    gemm_bf<<<gz, blk, SMEM_DYN>>>(xhi, xlo, Mthi, Mtlo, nullptr,
                                   (bf16*)zh16, (bf16*)zl16,
                                   DDIM, DDIM, DDIM, DDIM, 4, 0, 0, 0);

    // 3) Vt = Wv · xᵀ  (fp16 2-pass, fp16 out, coalesced)
    dim3 gv(MTOT / 128, DDIM / 128, 1);
    gemm_h2<<<gv, blk, H2_SMEM>>>(Wvh, Wvl, x16, nullptr, Vt16,
                                  DDIM, DDIM, MTOT, DDIM, 3, 0, 0, 0);

    // 4) scores = z · x16ᵀ per batch (fp16 2-pass, fp32 out)
    dim3 gsc(SLEN / 128, SLEN / 128, BATCH);
    gemm_h2<<<gsc, blk, H2_SMEM>>>(zh16, zl16, x16, Sc, nullptr,
                                   DDIM, DDIM, SLEN, DDIM, 0, sQKV, sQKV, sSS);

    // 5) softmax -> P fp16 rounded (BETA = 1)
    softmax_kernel16<<<MTOT, blk>>>(Sc, Ph);

    // 6) attended = P16 · Vt16ᵀ per batch (fp16 1-pass, fp32 out into d_out)
    dim3 gav(DDIM / 128, SLEN / 128, BATCH);
    gemm_h1<<<gav, blk, H1_SMEM>>>(Ph, Vt16, out,
                                   SLEN, MTOT, DDIM, SLEN,
                                   sSS, (size_t)SLEN, sQKV);

    // 7) y = attended + x; L2 normalize
    epilogue_kernel<<<MTOT, blk>>>(x, out);
}

// round 14
// speedup vs baseline: 1.9244x; 1.0488x over previous
#include <cuda_runtime.h>
#include <cuda_bf16.h>
#include <cuda_fp16.h>
#include <cstdint>
#include <cstddef>

#define BATCH   4
#define SLEN    4096
#define DDIM    1024
#define MTOT    (BATCH * SLEN)          // 16384

typedef __nv_bfloat16  bf16;
typedef __nv_bfloat162 bf162;

// ---------------------------------------------------------------------------
// Scratch (allocation-free rule: __device__ globals).
// z path (bf16 3-pass):   z = x·M, M = Wqᵀ·Wk           (K projection gone)
// scores (fp16 2-pass):   scores = (zh+zl)·x16ᵀ
// PV path (fp16 1-pass):  Vᵀ = Wvh·x16ᵀ, attended = P16·Vᵀᵀ
// ---------------------------------------------------------------------------
__device__ bf16 g_xhi [(size_t)MTOT * DDIM];
__device__ bf16 g_xlo [(size_t)MTOT * DDIM];
__device__ bf16 g_Wqthi[(size_t)DDIM * DDIM];
__device__ bf16 g_Wqtlo[(size_t)DDIM * DDIM];
__device__ bf16 g_Wkthi[(size_t)DDIM * DDIM];
__device__ bf16 g_Wktlo[(size_t)DDIM * DDIM];
__device__ bf16 g_Mthi[(size_t)DDIM * DDIM];
__device__ bf16 g_Mtlo[(size_t)DDIM * DDIM];
__device__ float g_S  [(size_t)MTOT * SLEN];
// fp16 operands
__device__ __half g_x16 [(size_t)MTOT * DDIM];   // x rounded to fp16
__device__ __half g_zh16[(size_t)MTOT * DDIM];   // z split fp16
__device__ __half g_zl16[(size_t)MTOT * DDIM];
__device__ __half g_Wvh [(size_t)DDIM * DDIM];   // Wv rounded fp16
__device__ __half g_Vt16[(size_t)DDIM * MTOT];   // Vᵀ fp16 [D, MTOT]
__device__ __half g_Ph  [(size_t)MTOT * SLEN];   // P rounded fp16

// ---------------------------------------------------------------------------
// Helpers (arch-agnostic PTX only: plain sm_103 target)
// ---------------------------------------------------------------------------
__device__ __forceinline__ uint32_t smem_u32(const void* p) {
    uint32_t a;
    asm("{ .reg .u64 t; cvta.to.shared.u64 t, %1; cvt.u32.u64 %0, t; }" : "=r"(a) : "l"(p));
    return a;
}
__device__ __forceinline__ void ldsm4(uint32_t& r0, uint32_t& r1, uint32_t& r2, uint32_t& r3,
                                      uint32_t addr) {
    asm volatile("ldmatrix.sync.aligned.m8n8.x4.shared.b16 {%0,%1,%2,%3}, [%4];"
                 : "=r"(r0), "=r"(r1), "=r"(r2), "=r"(r3) : "r"(addr));
}
__device__ __forceinline__ void mma16816(float* c, const uint32_t* a, const uint32_t* b) {
    asm volatile(
        "mma.sync.aligned.m16n8k16.row.col.f32.bf16.bf16.f32 "
        "{%0,%1,%2,%3}, {%4,%5,%6,%7}, {%8,%9}, {%0,%1,%2,%3};"
        : "+f"(c[0]), "+f"(c[1]), "+f"(c[2]), "+f"(c[3])
        : "r"(a[0]), "r"(a[1]), "r"(a[2]), "r"(a[3]), "r"(b[0]), "r"(b[1]));
}
__device__ __forceinline__ void mma16816h(float* c, const uint32_t* a, const uint32_t* b) {
    asm volatile(
        "mma.sync.aligned.m16n8k16.row.col.f32.f16.f16.f32 "
        "{%0,%1,%2,%3}, {%4,%5,%6,%7}, {%8,%9}, {%0,%1,%2,%3};"
        : "+f"(c[0]), "+f"(c[1]), "+f"(c[2]), "+f"(c[3])
        : "r"(a[0]), "r"(a[1]), "r"(a[2]), "r"(a[3]), "r"(b[0]), "r"(b[1]));
}
__device__ __forceinline__ void cpasync16(uint32_t dst, const void* src) {
    asm volatile("cp.async.cg.shared.global [%0], [%1], 16;" :: "r"(dst), "l"(src));
}
__device__ __forceinline__ void split2(float x, float y, bf162& h, bf162& l) {
    h = __floats2bfloat162_rn(x, y);
    float2 f = __bfloat1622float2(h);
    l = __floats2bfloat162_rn(x - f.x, y - f.y);
}
__device__ __forceinline__ void split2h(float x, float y, __half2& h, __half2& l) {
    h = __floats2half2_rn(x, y);
    float2 f = __half22float2(h);
    l = __floats2half2_rn(x - f.x, y - f.y);
}

// ---------------------------------------------------------------------------
// Fused conversion for x: one read -> bf16 hi/lo + fp16 rounded.
// ---------------------------------------------------------------------------
__global__ __launch_bounds__(256) void conv_x(
    const float* __restrict__ src, bf16* __restrict__ hi, bf16* __restrict__ lo,
    __half* __restrict__ h16)
{
    size_t i = ((size_t)blockIdx.x * 256 + threadIdx.x) * 4;
    float4 v = *(const float4*)(src + i);
    bf162 h0, l0, h1, l1;
    split2(v.x, v.y, h0, l0);
    split2(v.z, v.w, h1, l1);
    *(bf162*)(hi + i)     = h0;
    *(bf162*)(hi + i + 2) = h1;
    *(bf162*)(lo + i)     = l0;
    *(bf162*)(lo + i + 2) = l1;
    *(__half2*)(h16 + i)     = __floats2half2_rn(v.x, v.y);
    *(__half2*)(h16 + i + 2) = __floats2half2_rn(v.z, v.w);
}

__global__ __launch_bounds__(256) void conv_round16(
    const float* __restrict__ src, __half* __restrict__ dst)
{
    size_t i = ((size_t)blockIdx.x * 256 + threadIdx.x) * 4;
    float4 v = *(const float4*)(src + i);
    *(__half2*)(dst + i)     = __floats2half2_rn(v.x, v.y);
    *(__half2*)(dst + i + 2) = __floats2half2_rn(v.z, v.w);
}

// Transpose + split: out[i,e] = src[e,i] for 1024x1024 fp32, bf16 hi/lo out.
__global__ __launch_bounds__(256) void trans_split(
    const float* __restrict__ src, bf16* __restrict__ hi, bf16* __restrict__ lo)
{
    __shared__ float t[32][33];
    const int tx = threadIdx.x & 31;
    const int ty = threadIdx.x >> 5;
    const int bx = blockIdx.x * 32;
    const int by = blockIdx.y * 32;
    #pragma unroll
    for (int i = 0; i < 4; i++)
        t[ty + i * 8][tx] = src[(size_t)(by + ty + i * 8) * DDIM + bx + tx];
    __syncthreads();
    #pragma unroll
    for (int i = 0; i < 4; i++) {
        const int r = ty + i * 8;
        float v = t[tx][r];
        bf16 h = __float2bfloat16_rn(v);
        bf16 l = __float2bfloat16_rn(v - __bfloat162float(h));
        hi[(size_t)(bx + r) * DDIM + by + tx] = h;
        lo[(size_t)(bx + r) * DDIM + by + tx] = l;
    }
}

// ---------------------------------------------------------------------------
// bf16 NT GEMM, 3-pass fp32 emulation. 128x128, KC=32, 2-stage cp.async,
// 2 CTAs/SM. mode 0: fp32 C. mode 1: bf16 hi/lo out. mode 4: fp16 hi/lo out.
// ---------------------------------------------------------------------------
#define KC       32
#define LDT      40
#define MAT_B    (128 * LDT * 2)            // 10240 B
#define STAGE_B  (4 * MAT_B)                // 40960 B
#define SMEM_DYN (2 * STAGE_B)              // 81920 B

__global__ __launch_bounds__(256, 2) void gemm_bf(
    const bf16* __restrict__ Ahi, const bf16* __restrict__ Alo,
    const bf16* __restrict__ Bhi, const bf16* __restrict__ Blo,
    float* __restrict__ Cf, bf16* __restrict__ Chi, bf16* __restrict__ Clo,
    int lda, int ldb, int ldc, int K, int mode,
    size_t sA, size_t sB, size_t sC)
{
    extern __shared__ char smem[];
    Ahi += (size_t)blockIdx.z * sA;  Alo += (size_t)blockIdx.z * sA;
    Bhi += (size_t)blockIdx.z * sB;  Blo += (size_t)blockIdx.z * sB;

    const int tid  = threadIdx.x;
    const int lane = tid & 31;
    const int wid  = tid >> 5;
    const int bm   = blockIdx.y * 128;
    const int bn   = blockIdx.x * 128;
    const int m_warp = (wid & 3) * 32;
    const int n_warp = (wid >> 2) * 64;

    const uint32_t sbase = smem_u32(smem);
    const uint32_t aoff = (uint32_t)((m_warp + (lane & 15)) * (LDT * 2) + ((lane >> 4) * 8) * 2);
    const uint32_t boff = (uint32_t)((n_warp + (lane & 7) + ((lane & 16) ? 8 : 0)) * (LDT * 2)
                                     + ((lane & 8) ? 8 : 0) * 2);

    float acc[2][8][4];
    #pragma unroll
    for (int t = 0; t < 2; t++)
        #pragma unroll
        for (int n = 0; n < 8; n++)
            #pragma unroll
            for (int q = 0; q < 4; q++) acc[t][n][q] = 0.0f;

    const int nk = K / KC;

    auto issue = [&](int buf, int c) {
        const int k0 = c * KC;
        const uint32_t sb = sbase + buf * STAGE_B;
        #pragma unroll
        for (int i = 0; i < 2; i++) {
            const int l   = tid + i * 256;
            const int row = l >> 2;
            const int ch  = (l & 3) * 16;
            const uint32_t soff = (uint32_t)(row * (LDT * 2)) + ch;
            const size_t ga = (size_t)(bm + row) * lda + k0;
            const size_t gb = (size_t)(bn + row) * ldb + k0;
            cpasync16(sb + 0 * MAT_B + soff, (const char*)(Ahi + ga) + ch);
            cpasync16(sb + 1 * MAT_B + soff, (const char*)(Alo + ga) + ch);
            cpasync16(sb + 2 * MAT_B + soff, (const char*)(Bhi + gb) + ch);
            cpasync16(sb + 3 * MAT_B + soff, (const char*)(Blo + gb) + ch);
        }
    };

    auto compute = [&](int buf) {
        const uint32_t base = sbase + buf * STAGE_B;
        #pragma unroll
        for (int ks = 0; ks < 2; ks++) {
            const uint32_t kb = (uint32_t)ks * 32;
            uint32_t bh[4][4], bl[4][4];
            #pragma unroll
            for (int u = 0; u < 4; u++) {
                ldsm4(bh[u][0], bh[u][1], bh[u][2], bh[u][3],
                      base + 2 * MAT_B + boff + u * (16 * LDT * 2) + kb);
                ldsm4(bl[u][0], bl[u][1], bl[u][2], bl[u][3],
                      base + 3 * MAT_B + boff + u * (16 * LDT * 2) + kb);
            }
            #pragma unroll
            for (int t = 0; t < 2; t++) {
                uint32_t ah[4], al[4];
                ldsm4(ah[0], ah[1], ah[2], ah[3],
                      base + 0 * MAT_B + aoff + t * (16 * LDT * 2) + kb);
                ldsm4(al[0], al[1], al[2], al[3],
                      base + 1 * MAT_B + aoff + t * (16 * LDT * 2) + kb);
                #pragma unroll
                for (int n = 0; n < 8; n++)
                    mma16816(acc[t][n], ah, &bh[n >> 1][(n & 1) * 2]);
                #pragma unroll
                for (int n = 0; n < 8; n++)
                    mma16816(acc[t][n], ah, &bl[n >> 1][(n & 1) * 2]);
                #pragma unroll
                for (int n = 0; n < 8; n++)
                    mma16816(acc[t][n], al, &bh[n >> 1][(n & 1) * 2]);
            }
        }
    };

    issue(0, 0);
    asm volatile("cp.async.commit_group;" ::: "memory");

    for (int c = 0; c < nk; ++c) {
        asm volatile("cp.async.wait_group 0;" ::: "memory");
        __syncthreads();
        if (c + 1 < nk) {
            issue((c + 1) & 1, c + 1);
            asm volatile("cp.async.commit_group;" ::: "memory");
        }
        compute(c & 1);
    }

    #pragma unroll
    for (int t = 0; t < 2; t++)
        #pragma unroll
        for (int n = 0; n < 8; n++) {
            const int row = bm + m_warp + t * 16 + (lane >> 2);
            const int col = bn + n_warp + n * 8 + (lane & 3) * 2;
            if (mode == 0) {
                float* C0 = Cf + (size_t)blockIdx.z * sC;
                *(float2*)(C0 + (size_t)row * ldc + col) =
                    make_float2(acc[t][n][0], acc[t][n][1]);
                *(float2*)(C0 + (size_t)(row + 8) * ldc + col) =
                    make_float2(acc[t][n][2], acc[t][n][3]);
            } else if (mode == 1) {
                bf162 h, l;
                split2(acc[t][n][0], acc[t][n][1], h, l);
                *(bf162*)(Chi + (size_t)row * ldc + col) = h;
                *(bf162*)(Clo + (size_t)row * ldc + col) = l;
                split2(acc[t][n][2], acc[t][n][3], h, l);
                *(bf162*)(Chi + (size_t)(row + 8) * ldc + col) = h;
                *(bf162*)(Clo + (size_t)(row + 8) * ldc + col) = l;
            } else {   // mode 4: fp16 hi/lo via reinterpreted pointers
                __half* Hh = (__half*)Chi;
                __half* Hl = (__half*)Clo;
                __half2 h, l;
                split2h(acc[t][n][0], acc[t][n][1], h, l);
                *(__half2*)(Hh + (size_t)row * ldc + col) = h;
                *(__half2*)(Hl + (size_t)row * ldc + col) = l;
                split2h(acc[t][n][2], acc[t][n][3], h, l);
                *(__half2*)(Hh + (size_t)(row + 8) * ldc + col) = h;
                *(__half2*)(Hl + (size_t)(row + 8) * ldc + col) = l;
            }
        }
}

// ---------------------------------------------------------------------------
// fp16 NT GEMM, 2-pass (A split fp16, B rounded fp16). mode 0: fp32 C.
// ---------------------------------------------------------------------------
#define H2_STAGE (3 * MAT_B)                // Ah, Al, Bh = 30720 B
#define H2_SMEM  (2 * H2_STAGE)             // 61440 B

__global__ __launch_bounds__(256, 2) void gemm_h2(
    const __half* __restrict__ Ah, const __half* __restrict__ Al,
    const __half* __restrict__ Bh,
    float* __restrict__ Cf,
    int lda, int ldb, int ldc, int K,
    size_t sA, size_t sB, size_t sC)
{
    extern __shared__ char smem[];
    Ah += (size_t)blockIdx.z * sA;  Al += (size_t)blockIdx.z * sA;
    Bh += (size_t)blockIdx.z * sB;

    const int tid  = threadIdx.x;
    const int lane = tid & 31;
    const int wid  = tid >> 5;
    const int bm   = blockIdx.y * 128;
    const int bn   = blockIdx.x * 128;
    const int m_warp = (wid & 3) * 32;
    const int n_warp = (wid >> 2) * 64;

    const uint32_t sbase = smem_u32(smem);
    const uint32_t aoff = (uint32_t)((m_warp + (lane & 15)) * (LDT * 2) + ((lane >> 4) * 8) * 2);
    const uint32_t boff = (uint32_t)((n_warp + (lane & 7) + ((lane & 16) ? 8 : 0)) * (LDT * 2)
                                     + ((lane & 8) ? 8 : 0) * 2);

    float acc[2][8][4];
    #pragma unroll
    for (int t = 0; t < 2; t++)
        #pragma unroll
        for (int n = 0; n < 8; n++)
            #pragma unroll
            for (int q = 0; q < 4; q++) acc[t][n][q] = 0.0f;

    const int nk = K / KC;

    auto issue = [&](int buf, int c) {
        const int k0 = c * KC;
        const uint32_t sb = sbase + buf * H2_STAGE;
        #pragma unroll
        for (int i = 0; i < 2; i++) {
            const int l   = tid + i * 256;
            const int row = l >> 2;
            const int ch  = (l & 3) * 16;
            const uint32_t soff = (uint32_t)(row * (LDT * 2)) + ch;
            const size_t ga = (size_t)(bm + row) * lda + k0;
            const size_t gb = (size_t)(bn + row) * ldb + k0;
            cpasync16(sb + 0 * MAT_B + soff, (const char*)(Ah + ga) + ch);
            cpasync16(sb + 1 * MAT_B + soff, (const char*)(Al + ga) + ch);
            cpasync16(sb + 2 * MAT_B + soff, (const char*)(Bh + gb) + ch);
        }
    };

    auto compute = [&](int buf) {
        const uint32_t base = sbase + buf * H2_STAGE;
        #pragma unroll
        for (int ks = 0; ks < 2; ks++) {
            const uint32_t kb = (uint32_t)ks * 32;
            uint32_t bh[4][4];
            #pragma unroll
            for (int u = 0; u < 4; u++)
                ldsm4(bh[u][0], bh[u][1], bh[u][2], bh[u][3],
                      base + 2 * MAT_B + boff + u * (16 * LDT * 2) + kb);
            #pragma unroll
            for (int t = 0; t < 2; t++) {
                uint32_t ah[4], al[4];
                ldsm4(ah[0], ah[1], ah[2], ah[3],
                      base + 0 * MAT_B + aoff + t * (16 * LDT * 2) + kb);
                ldsm4(al[0], al[1], al[2], al[3],
                      base + 1 * MAT_B + aoff + t * (16 * LDT * 2) + kb);
                #pragma unroll
                for (int n = 0; n < 8; n++)
                    mma16816h(acc[t][n], ah, &bh[n >> 1][(n & 1) * 2]);
                #pragma unroll
                for (int n = 0; n < 8; n++)
                    mma16816h(acc[t][n], al, &bh[n >> 1][(n & 1) * 2]);
            }
        }
    };

    issue(0, 0);
    asm volatile("cp.async.commit_group;" ::: "memory");

    for (int c = 0; c < nk; ++c) {
        asm volatile("cp.async.wait_group 0;" ::: "memory");
        __syncthreads();
        if (c + 1 < nk) {
            issue((c + 1) & 1, c + 1);
            asm volatile("cp.async.commit_group;" ::: "memory");
        }
        compute(c & 1);
    }

    #pragma unroll
    for (int t = 0; t < 2; t++)
        #pragma unroll
        for (int n = 0; n < 8; n++) {
            const int row = bm + m_warp + t * 16 + (lane >> 2);
            const int col = bn + n_warp + n * 8 + (lane & 3) * 2;
            float* C0 = Cf + (size_t)blockIdx.z * sC;
            *(float2*)(C0 + (size_t)row * ldc + col) =
                make_float2(acc[t][n][0], acc[t][n][1]);
            *(float2*)(C0 + (size_t)(row + 8) * ldc + col) =
                make_float2(acc[t][n][2], acc[t][n][3]);
        }
}

// ---------------------------------------------------------------------------
// fp16 NT GEMM, 1-pass (A rounded, B rounded). mode 0: fp32 C. mode 3: fp16 C.
// ---------------------------------------------------------------------------
#define H1_STAGE (2 * MAT_B)                // Ah, Bh = 20480 B
#define H1_SMEM  (2 * H1_STAGE)             // 40960 B

__global__ __launch_bounds__(256, 2) void gemm_h1(
    const __half* __restrict__ Ah, const __half* __restrict__ Bh,
    float* __restrict__ Cf, __half* __restrict__ C16,
    int lda, int ldb, int ldc, int K, int mode,
    size_t sA, size_t sB, size_t sC)
{
    extern __shared__ char smem[];
    Ah += (size_t)blockIdx.z * sA;
    Bh += (size_t)blockIdx.z * sB;

    const int tid  = threadIdx.x;
    const int lane = tid & 31;
    const int wid  = tid >> 5;
    const int bm   = blockIdx.y * 128;
    const int bn   = blockIdx.x * 128;
    const int m_warp = (wid & 3) * 32;
    const int n_warp = (wid >> 2) * 64;

    const uint32_t sbase = smem_u32(smem);
    const uint32_t aoff = (uint32_t)((m_warp + (lane & 15)) * (LDT * 2) + ((lane >> 4) * 8) * 2);
    const uint32_t boff = (uint32_t)((n_warp + (lane & 7) + ((lane & 16) ? 8 : 0)) * (LDT * 2)
                                     + ((lane & 8) ? 8 : 0) * 2);

    float acc[2][8][4];
    #pragma unroll
    for (int t = 0; t < 2; t++)
        #pragma unroll
        for (int n = 0; n < 8; n++)
            #pragma unroll
            for (int q = 0; q < 4; q++) acc[t][n][q] = 0.0f;

    const int nk = K / KC;

    auto issue = [&](int buf, int c) {
        const int k0 = c * KC;
        const uint32_t sb = sbase + buf * H1_STAGE;
        #pragma unroll
        for (int i = 0; i < 2; i++) {
            const int l   = tid + i * 256;
            const int row = l >> 2;
            const int ch  = (l & 3) * 16;
            const uint32_t soff = (uint32_t)(row * (LDT * 2)) + ch;
            const size_t ga = (size_t)(bm + row) * lda + k0;
            const size_t gb = (size_t)(bn + row) * ldb + k0;
            cpasync16(sb + 0 * MAT_B + soff, (const char*)(Ah + ga) + ch);
            cpasync16(sb + 1 * MAT_B + soff, (const char*)(Bh + gb) + ch);
        }
    };

    auto compute = [&](int buf) {
        const uint32_t base = sbase + buf * H1_STAGE;
        #pragma unroll
        for (int ks = 0; ks < 2; ks++) {
            const uint32_t kb = (uint32_t)ks * 32;
            uint32_t bh[4][4];
            #pragma unroll
            for (int u = 0; u < 4; u++)
                ldsm4(bh[u][0], bh[u][1], bh[u][2], bh[u][3],
                      base + 1 * MAT_B + boff + u * (16 * LDT * 2) + kb);
            #pragma unroll
            for (int t = 0; t < 2; t++) {
                uint32_t ah[4];
                ldsm4(ah[0], ah[1], ah[2], ah[3],
                      base + 0 * MAT_B + aoff + t * (16 * LDT * 2) + kb);
                #pragma unroll
                for (int n = 0; n < 8; n++)
                    mma16816h(acc[t][n], ah, &bh[n >> 1][(n & 1) * 2]);
            }
        }
    };

    issue(0, 0);
    asm volatile("cp.async.commit_group;" ::: "memory");

    for (int c = 0; c < nk; ++c) {
        asm volatile("cp.async.wait_group 0;" ::: "memory");
        __syncthreads();
        if (c + 1 < nk) {
            issue((c + 1) & 1, c + 1);
            asm volatile("cp.async.commit_group;" ::: "memory");
        }
        compute(c & 1);
    }

    #pragma unroll
    for (int t = 0; t < 2; t++)
        #pragma unroll
        for (int n = 0; n < 8; n++) {
            const int row = bm + m_warp + t * 16 + (lane >> 2);
            const int col = bn + n_warp + n * 8 + (lane & 3) * 2;
            if (mode == 0) {
                float* C0 = Cf + (size_t)blockIdx.z * sC;
                *(float2*)(C0 + (size_t)row * ldc + col) =
                    make_float2(acc[t][n][0], acc[t][n][1]);
                *(float2*)(C0 + (size_t)(row + 8) * ldc + col) =
                    make_float2(acc[t][n][2], acc[t][n][3]);
            } else {   // mode 3: fp16 rounded
                *(__half2*)(C16 + (size_t)row * ldc + col) =
                    __floats2half2_rn(acc[t][n][0], acc[t][n][1]);
                *(__half2*)(C16 + (size_t)(row + 8) * ldc + col) =
                    __floats2half2_rn(acc[t][n][2], acc[t][n][3]);
            }
        }
}

// ---------------------------------------------------------------------------
// Row softmax over 4096 fp32 scores -> fp16 rounded probabilities.
// ---------------------------------------------------------------------------
__global__ __launch_bounds__(256) void softmax_kernel16(
    const float* __restrict__ Sm, __half* __restrict__ Ph)
{
    const float* row = Sm + (size_t)blockIdx.x * SLEN;
    __half* ph = Ph + (size_t)blockIdx.x * SLEN;
    const int t    = threadIdx.x;
    const int lane = t & 31;
    const int warp = t >> 5;

    __shared__ float red[8];

    float v[16];
    float mx = -1e30f;
    #pragma unroll
    for (int i = 0; i < 16; i++) {
        v[i] = row[t + (i << 8)];
        mx = fmaxf(mx, v[i]);
    }
    #pragma unroll
    for (int o = 16; o > 0; o >>= 1)
        mx = fmaxf(mx, __shfl_xor_sync(0xffffffffu, mx, o));
    if (lane == 0) red[warp] = mx;
    __syncthreads();
    float rmax = red[0];
    #pragma unroll
    for (int i = 1; i < 8; i++) rmax = fmaxf(rmax, red[i]);

    float sum = 0.0f;
    #pragma unroll
    for (int i = 0; i < 16; i++) {
        v[i] = __expf(v[i] - rmax);
        sum += v[i];
    }
    #pragma unroll
    for (int o = 16; o > 0; o >>= 1)
        sum += __shfl_xor_sync(0xffffffffu, sum, o);
    __syncthreads();
    if (lane == 0) red[warp] = sum;
    __syncthreads();
    float rsum = 0.0f;
    #pragma unroll
    for (int i = 0; i < 8; i++) rsum += red[i];

    const float inv = 1.0f / rsum;
    #pragma unroll
    for (int i = 0; i < 16; i++)
        ph[t + (i << 8)] = __float2half_rn(v[i] * inv);
}

// ---------------------------------------------------------------------------
// Final epilogue: y = attended + x;  out = y / ||y||_2 per 1024-row.
// ---------------------------------------------------------------------------
__global__ __launch_bounds__(256) void epilogue_kernel(
    const float* __restrict__ x, float* __restrict__ out)
{
    const size_t base = (size_t)blockIdx.x * DDIM;
    const int t    = threadIdx.x;
    const int lane = t & 31;
    const int warp = t >> 5;

    __shared__ float red[8];

    float4 a  = *(const float4*)(out + base + t * 4);
    float4 xv = *(const float4*)(x   + base + t * 4);
    float y0 = a.x + xv.x, y1 = a.y + xv.y, y2 = a.z + xv.z, y3 = a.w + xv.w;

    float ss = y0 * y0 + y1 * y1 + y2 * y2 + y3 * y3;
    #pragma unroll
    for (int o = 16; o > 0; o >>= 1)
        ss += __shfl_xor_sync(0xffffffffu, ss, o);
    if (lane == 0) red[warp] = ss;
    __syncthreads();
    float tot = 0.0f;
    #pragma unroll
    for (int i = 0; i < 8; i++) tot += red[i];

    const float inv = 1.0f / sqrtf(tot);
    *(float4*)(out + base + t * 4) =
        make_float4(y0 * inv, y1 * inv, y2 * inv, y3 * inv);
}

// ---------------------------------------------------------------------------
// Launch
// ---------------------------------------------------------------------------
extern "C" void kernel_launch(void* const* d_in, const int* in_sizes, int n_in,
                              void* d_out, int out_size)
{
    const float* x  = (const float*)d_in[0];
    const float* Wq = (const float*)d_in[1];
    const float* Wk = (const float*)d_in[2];
    const float* Wv = (const float*)d_in[3];
    float* out = (float*)d_out;

    bf16 *xhi, *xlo, *Wqthi, *Wqtlo, *Wkthi, *Wktlo, *Mthi, *Mtlo;
    __half *x16, *zh16, *zl16, *Wvh, *Vt16, *Ph;
    float* Sc;
    cudaGetSymbolAddress((void**)&xhi,   g_xhi);    cudaGetSymbolAddress((void**)&xlo,   g_xlo);
    cudaGetSymbolAddress((void**)&Wqthi, g_Wqthi);  cudaGetSymbolAddress((void**)&Wqtlo, g_Wqtlo);
    cudaGetSymbolAddress((void**)&Wkthi, g_Wkthi);  cudaGetSymbolAddress((void**)&Wktlo, g_Wktlo);
    cudaGetSymbolAddress((void**)&Mthi,  g_Mthi);   cudaGetSymbolAddress((void**)&Mtlo,  g_Mtlo);
    cudaGetSymbolAddress((void**)&x16,   g_x16);
    cudaGetSymbolAddress((void**)&zh16,  g_zh16);   cudaGetSymbolAddress((void**)&zl16,  g_zl16);
    cudaGetSymbolAddress((void**)&Wvh,   g_Wvh);
    cudaGetSymbolAddress((void**)&Vt16,  g_Vt16);
    cudaGetSymbolAddress((void**)&Ph,    g_Ph);
    cudaGetSymbolAddress((void**)&Sc,    g_S);

    cudaFuncSetAttribute(gemm_bf, cudaFuncAttributeMaxDynamicSharedMemorySize, SMEM_DYN);
    cudaFuncSetAttribute(gemm_h2, cudaFuncAttributeMaxDynamicSharedMemorySize, H2_SMEM);
    cudaFuncSetAttribute(gemm_h1, cudaFuncAttributeMaxDynamicSharedMemorySize, H1_SMEM);

    const size_t sQKV = (size_t)SLEN * DDIM;
    const size_t sSS  = (size_t)SLEN * SLEN;
    dim3 blk(256);

    // 0) conversions (x fused: one read -> bf16 hi/lo + fp16)
    conv_x<<<(MTOT * DDIM) / 1024, blk>>>(x, xhi, xlo, x16);
    conv_round16<<<(DDIM * DDIM) / 1024, blk>>>(Wv, Wvh);
    dim3 gtr(DDIM / 32, DDIM / 32, 1);
    trans_split<<<gtr, blk>>>(Wq, Wqthi, Wqtlo);
    trans_split<<<gtr, blk>>>(Wk, Wkthi, Wktlo);

    // 1) Mt = Wkt · Wqtᵀ  (bf16 3-pass, bf16 hi/lo out)
    dim3 gM(DDIM / 128, DDIM / 128, 1);
    gemm_bf<<<gM, blk, SMEM_DYN>>>(Wkthi, Wktlo, Wqthi, Wqtlo, nullptr, Mthi, Mtlo,
                                   DDIM, DDIM, DDIM, DDIM, 1, 0, 0, 0);

    // 2) z = x · Mtᵀ  (bf16 3-pass, fp16 hi/lo out for the scores GEMM)
    dim3 gz(DDIM / 128, MTOT / 128, 1);
    gemm_bf<<<gz, blk, SMEM_DYN>>>(xhi, xlo, Mthi, Mtlo, nullptr,
                                   (bf16*)zh16, (bf16*)zl16,
                                   DDIM, DDIM, DDIM, DDIM, 4, 0, 0, 0);

    // 3) Vt = Wvh · x16ᵀ  (fp16 1-pass, fp16 out, coalesced)
    dim3 gv(MTOT / 128, DDIM / 128, 1);
    gemm_h1<<<gv, blk, H1_SMEM>>>(Wvh, x16, nullptr, Vt16,
                                  DDIM, DDIM, MTOT, DDIM, 3, 0, 0, 0);

    // 4) scores = z · x16ᵀ per batch (fp16 2-pass, fp32 out)
    dim3 gsc(SLEN / 128, SLEN / 128, BATCH);
    gemm_h2<<<gsc, blk, H2_SMEM>>>(zh16, zl16, x16, Sc,
                                   DDIM, DDIM, SLEN, DDIM, sQKV, sQKV, sSS);

    // 5) softmax -> P fp16 rounded (BETA = 1)
    softmax_kernel16<<<MTOT, blk>>>(Sc, Ph);

    // 6) attended = P16 · Vt16ᵀ per batch (fp16 1-pass, fp32 out into d_out)
    dim3 gav(DDIM / 128, SLEN / 128, BATCH);
    gemm_h1<<<gav, blk, H1_SMEM>>>(Ph, Vt16, out, nullptr,
                                   SLEN, MTOT, DDIM, SLEN, 0,
                                   sSS, (size_t)SLEN, sQKV);

    // 7) y = attended + x; L2 normalize
    epilogue_kernel<<<MTOT, blk>>>(x, out);
}